// round 12
// baseline (speedup 1.0000x reference)
#include <cuda_runtime.h>
#include <cstddef>
#include <cstdint>

typedef unsigned long long ull;

// Problem constants
#define A_ 4
#define B_ 8
#define S_ 2048
#define D_ 256
#define N_ 32      // A_*B_
#define H_ 256
#define G_ 1024    // 4*H_
#define CL 8       // cluster size

// -------- scratch (device globals; allocation-free per harness rules) --------
__device__ float g_f[(size_t)N_ * S_ * D_];
__device__ float g_xw0[(size_t)N_ * S_ * G_];
__device__ float g_xw1[(size_t)N_ * S_ * G_];
__device__ float g_hseq0[(size_t)S_ * N_ * H_];   // [t][n][j] layout
__device__ float g_hseq1[(size_t)S_ * N_ * H_];   // [t][n][j] layout
__device__ float g_hbuf[(size_t)N_ * S_ * D_];
__device__ float g_zp[B_ * D_];

__device__ __forceinline__ float fsig(float x) { return 1.f / (1.f + __expf(-x)); }
__device__ __forceinline__ float ftanh(float x) {
    float t = __expf(-2.f * fabsf(x));
    float r = (1.f - t) / (1.f + t);
    return copysignf(r, x);
}
// fast approx versions for the scan recurrence (MUFU tanh, sm_75+)
__device__ __forceinline__ float tanh_fast(float x) {
    float y; asm("tanh.approx.f32 %0, %1;" : "=f"(y) : "f"(x)); return y;
}
__device__ __forceinline__ float sig_fast(float x) {
    return fmaf(tanh_fast(0.5f * x), 0.5f, 0.5f);
}

// f32x2 packed FFMA (sm_103a; only reachable via PTX)
#define FMA2(acc, a, b) asm("fma.rn.f32x2 %0, %1, %2, %0;" : "+l"(acc) : "l"(a), "l"(b))
#define PACK2(out, lo, hi) \
    asm("mov.b64 %0, {%1, %2};" : "=l"(out) : "f"(lo), "f"(hi))
#define UNPK(lo, hi, v)                                                      \
    do { unsigned _a, _b;                                                    \
         asm("mov.b64 {%0, %1}, %2;" : "=r"(_a), "=r"(_b) : "l"(v));         \
         lo = __uint_as_float(_a); hi = __uint_as_float(_b); } while (0)

__device__ __forceinline__ unsigned ctarank() {
    unsigned r; asm("mov.u32 %0, %%cluster_ctarank;" : "=r"(r)); return r;
}
__device__ __forceinline__ unsigned smem_u32(const void* p) {
    return (unsigned)__cvta_generic_to_shared(p);
}
__device__ __forceinline__ unsigned mapa_u32(unsigned a, unsigned rank) {
    unsigned r;
    asm("mapa.shared::cluster.u32 %0, %1, %2;" : "=r"(r) : "r"(a), "r"(rank));
    return r;
}
__device__ __forceinline__ void st_cluster_f32(unsigned a, float v) {
    asm volatile("st.shared::cluster.f32 [%0], %1;" :: "r"(a), "f"(v) : "memory");
}
__device__ __forceinline__ void mbar_init(unsigned a, unsigned cnt) {
    asm volatile("mbarrier.init.shared.b64 [%0], %1;" :: "r"(a), "r"(cnt) : "memory");
}
__device__ __forceinline__ void mbar_arrive_cluster(unsigned a) {
    asm volatile("mbarrier.arrive.release.cluster.shared::cluster.b64 _, [%0];"
                 :: "r"(a) : "memory");
}
__device__ __forceinline__ void mbar_wait_cluster(unsigned a, unsigned parity) {
    asm volatile(
        "{\n\t.reg .pred P;\n\t"
        "W%=:\n\t"
        "mbarrier.try_wait.parity.acquire.cluster.shared::cta.b64 P, [%0], %1, 0x989680;\n\t"
        "@!P bra W%=;\n\t}"
        :: "r"(a), "r"(parity) : "memory");
}

// ------------------------- z / zp (tiny matvec) ------------------------------
__global__ void k_zzp(const float* __restrict__ hin, const float* __restrict__ W4,
                      const float* __restrict__ b4) {
    __shared__ float zs[D_];
    int b = blockIdx.x;
    int e = threadIdx.x;
    float s = 0.f;
#pragma unroll
    for (int a = 0; a < A_; ++a)
        s += hin[(((size_t)(a * B_ + b)) * S_ + (S_ - 1)) * D_ + e];
    zs[e] = s * (1.f / 3.f);
    __syncthreads();
    float acc = b4[e];
#pragma unroll 8
    for (int d = 0; d < D_; ++d) acc += zs[d] * W4[d * D_ + e];
    g_zp[b * D_ + e] = acc;
}

// ------------------------- SGEMM (double-buffered) ---------------------------
// C[M x NDIM] = op(A)[M x KDIM] @ Bw[KDIM x NDIM] + bias (+ optional zp + tanh)
// AMODE 0: A0[m][k]
// AMODE 1: A0[(n, S-1-s)][k]          (time-reversed rows; m = n*S+s)
// AMODE 3: concat from [t][n][j] layout:
//          k<256 -> A0[(s*32+n)][k] ; k>=256 -> A1[((S-1-s)*32+n)][k-256]
// EPI 0: +bias   EPI 1: tanh(v + bias + g_zp[b])
template <int AMODE, int EPI, int KDIM, int NDIM>
__global__ void __launch_bounds__(256, 2)
k_gemm(const float* __restrict__ A0, const float* __restrict__ A1,
       const float* __restrict__ Bw, const float* __restrict__ bias,
       float* __restrict__ C) {
    __shared__ float As[2][8][128];
    __shared__ float Bs[2][8][128];
    const int tid = threadIdx.x;
    const int m0 = blockIdx.y * 128;
    const int n0 = blockIdx.x * 128;
    const int aRow = tid >> 1;
    const int aCol = (tid & 1) * 4;
    const int bRow = tid >> 5;
    const int bCol = (tid & 31) * 4;
    const int tr = (tid >> 4) * 8;
    const int tc = (tid & 15) * 8;

    const int m = m0 + aRow;
    const float* aP0;
    const float* aP1 = nullptr;
    if (AMODE == 0) {
        aP0 = A0 + (size_t)m * KDIM;
    } else if (AMODE == 1) {
        int n = m >> 11, s = m & 2047;
        aP0 = A0 + ((size_t)(n << 11) + (2047 - s)) * KDIM;
    } else {
        int n = m >> 11, s = m & 2047;
        aP0 = A0 + ((size_t)(s * 32) + n) * 256;
        aP1 = A1 + ((size_t)((2047 - s) * 32) + n) * 256;
    }
    const float* bP = Bw + (size_t)bRow * NDIM + n0 + bCol;

    float acc[8][8];
#pragma unroll
    for (int i = 0; i < 8; ++i)
#pragma unroll
        for (int j = 0; j < 8; ++j) acc[i][j] = 0.f;

    auto loadA = [&](int k0) -> float4 {
        if (AMODE != 3) {
            return *(const float4*)(aP0 + k0 + aCol);
        } else {
            int kk = k0 + aCol;
            return (kk < 256) ? *(const float4*)(aP0 + kk)
                              : *(const float4*)(aP1 + (kk - 256));
        }
    };
    auto loadB = [&](int k0) -> float4 {
        return *(const float4*)(bP + (size_t)k0 * NDIM);
    };

    constexpr int NT = KDIM / 8;

    {
        float4 av = loadA(0);
        float4 bv = loadB(0);
        As[0][aCol + 0][aRow] = av.x;
        As[0][aCol + 1][aRow] = av.y;
        As[0][aCol + 2][aRow] = av.z;
        As[0][aCol + 3][aRow] = av.w;
        *(float4*)&Bs[0][bRow][bCol] = bv;
    }
    __syncthreads();

    for (int t = 0; t < NT; ++t) {
        const int cur = t & 1;
        float4 av, bv;
        if (t + 1 < NT) {
            av = loadA((t + 1) * 8);
            bv = loadB((t + 1) * 8);
        }
#pragma unroll
        for (int kk = 0; kk < 8; ++kk) {
            float ra[8], rb[8];
            *(float4*)(ra)     = *(const float4*)&As[cur][kk][tr];
            *(float4*)(ra + 4) = *(const float4*)&As[cur][kk][tr + 4];
            *(float4*)(rb)     = *(const float4*)&Bs[cur][kk][tc];
            *(float4*)(rb + 4) = *(const float4*)&Bs[cur][kk][tc + 4];
#pragma unroll
            for (int i = 0; i < 8; ++i)
#pragma unroll
                for (int j = 0; j < 8; ++j) acc[i][j] += ra[i] * rb[j];
        }
        if (t + 1 < NT) {
            const int nxt = cur ^ 1;
            As[nxt][aCol + 0][aRow] = av.x;
            As[nxt][aCol + 1][aRow] = av.y;
            As[nxt][aCol + 2][aRow] = av.z;
            As[nxt][aCol + 3][aRow] = av.w;
            *(float4*)&Bs[nxt][bRow][bCol] = bv;
            __syncthreads();
        }
    }

#pragma unroll
    for (int i = 0; i < 8; ++i) {
        int mm = m0 + tr + i;
        float* crow = C + (size_t)mm * NDIM + n0 + tc;
        int bi = 0;
        if (EPI == 1) bi = (mm >> 11) & 7;
#pragma unroll
        for (int j4 = 0; j4 < 8; j4 += 4) {
            int col = n0 + tc + j4;
            float4 v = make_float4(acc[i][j4], acc[i][j4 + 1], acc[i][j4 + 2], acc[i][j4 + 3]);
            v.x += bias[col]; v.y += bias[col + 1]; v.z += bias[col + 2]; v.w += bias[col + 3];
            if (EPI == 1) {
                const float* zr = &g_zp[bi * D_];
                v.x = ftanh(v.x + zr[col]);     v.y = ftanh(v.y + zr[col + 1]);
                v.z = ftanh(v.z + zr[col + 2]); v.w = ftanh(v.w + zr[col + 3]);
            }
            *(float4*)(crow + j4) = v;
        }
    }
}

// ---- cluster LSTM scan: shuffle reduction, pair-barriers, 2 CTAs per SM -----
// 32 clusters x 8 CTAs. Cluster c: dir = c>>4, grp = c&15 -> seqs {2grp,2grp+1}.
// CTA rank r owns hidden units [32r, 32r+32). Thread map: tid = u*8+gate*2+kh
// (u = unit-in-slice, gate 0..3, kh = K-half). Each thread computes its gate
// column for BOTH seqs over its K-half: 128 FMA2 (weights: 32 f32x2 pairs in
// regs + 32 pairs in smem, LDS.128-vectorized). Reduction entirely in-warp:
// kh partner = lane^1, gate partners = lane^2/^4 -> 8 SHFLs, no smem red[],
// ONE __syncthreads per step. Waits: 4 pair-barriers (count=2; sources r and
// r+4 arrive on barrier r&3) -> warp-uniform wait addresses, 4 waits/step.
// Activations/MUFU/pushes only in the 32 lanes with tid%8==0.
#define SCAN_SMEM (4096 + 64 + 65536)
__global__ void __launch_bounds__(256, 2) __cluster_dims__(CL, 1, 1)
k_scan(const float* __restrict__ Whf, const float* __restrict__ Whb) {
    extern __shared__ __align__(16) char smx[];
    float* hbuf = (float*)smx;              // [buf][s][unit] 2*2*256 = 4KB
    ull*   mbar = (ull*)(smx + 4096);       // [pair][buf] 4*2
    ull*   Ws   = (ull*)(smx + 4160);       // [tid][32] = 64KB

    const int tid = threadIdx.x;
    const unsigned rank = ctarank();
    const int cid = blockIdx.x >> 3;
    const int dir = cid >> 4;
    const int grp = cid & 15;
    const float* Wh   = dir ? Whb : Whf;
    const float* xw   = dir ? g_xw1 : g_xw0;
    float*       hseq = dir ? g_hseq1 : g_hseq0;
    const int ju0 = (int)rank * 32;

    const int kh   = tid & 1;
    const int gate = (tid >> 1) & 3;
    const int u    = tid >> 3;
    const int gcol = gate * 256 + ju0 + u;

    if (tid < 8)
        mbar_init(smem_u32(&mbar[0]) + (unsigned)tid * 8, 2);

    // ---- Wh slice: pairs 0..31 of this K-half in regs, 32..63 in smem ----
    ull W2[32];
#pragma unroll
    for (int k2 = 0; k2 < 32; ++k2) {
        const int k = kh * 128 + 2 * k2;
        float lo = __ldg(Wh + (size_t)k * G_ + gcol);
        float hi = __ldg(Wh + (size_t)(k + 1) * G_ + gcol);
        PACK2(W2[k2], lo, hi);
    }
    for (int k2 = 0; k2 < 32; ++k2) {
        const int k = kh * 128 + 2 * (32 + k2);
        float lo = __ldg(Wh + (size_t)k * G_ + gcol);
        float hi = __ldg(Wh + (size_t)(k + 1) * G_ + gcol);
        ull w; PACK2(w, lo, hi);
        Ws[tid * 32 + k2] = w;
    }
    __syncthreads();
    // barriers must be initialized cluster-wide before first arrive
    asm volatile("barrier.cluster.arrive.aligned;" ::: "memory");
    asm volatile("barrier.cluster.wait.aligned;" ::: "memory");

    // ---- push / arrive addresses ----
    unsigned pa[CL];
    {
        unsigned la = smem_u32(&hbuf[ju0 + u]);   // hbuf[0][0][ju0+u]
#pragma unroll
        for (unsigned r = 0; r < CL; ++r) pa[r] = mapa_u32(la, r);
    }
    unsigned amD = 0;
    if (tid < CL)
        amD = mapa_u32(smem_u32(&mbar[(rank & 3) * 2]), (unsigned)tid);
    const unsigned mb = smem_u32(&mbar[0]);
    const int nG0 = grp * 2;
    const float* xrow0 = xw + (size_t)nG0 * S_ * G_ + gcol;
    float creg0 = 0.f, creg1 = 0.f;

    for (int t = 0; t < S_; ++t) {
        const int buf = t & 1;

        // prefetch this step's input projections (own gate, both seqs)
        float x0 = __ldcg(xrow0 + (size_t)t * G_);
        float x1 = __ldcg(xrow0 + (size_t)(S_ + t) * G_);

        ull a0 = 0ull, a1 = 0ull;
        if (t > 0) {
            const unsigned par = (unsigned)(((t - 1) >> 1) & 1);
            const unsigned pb  = (unsigned)((t - 1) & 1);
            const float* hb = hbuf + (buf ^ 1) * 512 + kh * 128;
#define CHUNK(ci)                                                             \
            {                                                                 \
                mbar_wait_cluster(mb + ((ci) * 2 + pb) * 8, par);             \
                const float* hc = hb + (ci) * 32;                             \
                _Pragma("unroll")                                             \
                for (int q = 0; q < 4; ++q) {                                 \
                    const float* h0 = hc + q * 8;                             \
                    ulonglong2 A0 = *(const ulonglong2*)h0;                   \
                    ulonglong2 B0 = *(const ulonglong2*)(h0 + 4);             \
                    ulonglong2 A1v = *(const ulonglong2*)(h0 + 256);          \
                    ulonglong2 B1v = *(const ulonglong2*)(h0 + 260);          \
                    ull w0, w1, w2, w3;                                       \
                    if ((ci) < 2) {                                           \
                        w0 = W2[(ci) * 16 + q * 4 + 0];                       \
                        w1 = W2[(ci) * 16 + q * 4 + 1];                       \
                        w2 = W2[(ci) * 16 + q * 4 + 2];                       \
                        w3 = W2[(ci) * 16 + q * 4 + 3];                       \
                    } else {                                                  \
                        const ulonglong2* wp = (const ulonglong2*)            \
                            (Ws + tid * 32 + ((ci) - 2) * 16 + q * 4);        \
                        ulonglong2 wA = wp[0], wB = wp[1];                    \
                        w0 = wA.x; w1 = wA.y; w2 = wB.x; w3 = wB.y;           \
                    }                                                         \
                    FMA2(a0, w0, A0.x); FMA2(a0, w1, A0.y);                   \
                    FMA2(a0, w2, B0.x); FMA2(a0, w3, B0.y);                   \
                    FMA2(a1, w0, A1v.x); FMA2(a1, w1, A1v.y);                 \
                    FMA2(a1, w2, B1v.x); FMA2(a1, w3, B1v.y);                 \
                }                                                             \
            }
            CHUNK(0) CHUNK(1) CHUNK(2) CHUNK(3)
#undef CHUNK
        }

        // ---- in-warp reduction: kh (lane^1), then gate gather (^2, ^4) ----
        float f0, f1;
        UNPK(f0, f1, a0); float g0 = f0 + f1;
        UNPK(f0, f1, a1); float g1 = f0 + f1;
        g0 += __shfl_xor_sync(0xffffffffu, g0, 1);
        g1 += __shfl_xor_sync(0xffffffffu, g1, 1);
        g0 += x0;
        g1 += x1;

        float t1 = __shfl_xor_sync(0xffffffffu, g0, 2);
        float ga = (gate & 1) ? t1 : g0;
        float gb = (gate & 1) ? g0 : t1;
        float t2 = __shfl_xor_sync(0xffffffffu, ga, 4);
        float t3 = __shfl_xor_sync(0xffffffffu, gb, 4);
        float qi0 = (gate < 2) ? ga : t2;
        float qf0 = (gate < 2) ? gb : t3;
        float qg0 = (gate < 2) ? t2 : ga;
        float qo0 = (gate < 2) ? t3 : gb;

        t1 = __shfl_xor_sync(0xffffffffu, g1, 2);
        ga = (gate & 1) ? t1 : g1;
        gb = (gate & 1) ? g1 : t1;
        t2 = __shfl_xor_sync(0xffffffffu, ga, 4);
        t3 = __shfl_xor_sync(0xffffffffu, gb, 4);
        float qi1 = (gate < 2) ? ga : t2;
        float qf1 = (gate < 2) ? gb : t3;
        float qg1 = (gate < 2) ? t2 : ga;
        float qo1 = (gate < 2) ? t3 : gb;

        if ((tid & 7) == 0) {
            float ii = sig_fast(qi0), ff = sig_fast(qf0);
            float gg = tanh_fast(qg0), oo = sig_fast(qo0);
            creg0 = ff * creg0 + ii * gg;
            float hv0 = oo * tanh_fast(creg0);

            ii = sig_fast(qi1); ff = sig_fast(qf1);
            gg = tanh_fast(qg1); oo = sig_fast(qo1);
            creg1 = ff * creg1 + ii * gg;
            float hv1 = oo * tanh_fast(creg1);

            float* hs = &hseq[((size_t)t * N_ + nG0) * H_ + ju0 + u];
            __stcg(hs, hv0);
            __stcg(hs + H_, hv1);
            if (t < S_ - 1) {
                const unsigned boff = (unsigned)buf << 11;   // buf*2048 bytes
#pragma unroll
                for (int r = 0; r < CL; ++r) {
                    st_cluster_f32(pa[r] + boff, hv0);
                    st_cluster_f32(pa[r] + boff + 1024u, hv1);
                }
            }
        }
        __syncthreads();   // all pushes ordered before the release-arrives
        if (t < S_ - 1 && tid < CL)
            mbar_arrive_cluster(amD + (unsigned)buf * 8);
    }

    if (tid == 0) {
#pragma unroll
        for (int i = 0; i < 8; ++i)
            asm volatile("mbarrier.inval.shared.b64 [%0];"
                         :: "r"(smem_u32(&mbar[0]) + i * 8) : "memory");
    }
    // no CTA may exit while peers might still push into its smem
    asm volatile("barrier.cluster.arrive.aligned;" ::: "memory");
    asm volatile("barrier.cluster.wait.aligned;" ::: "memory");
}

// ------------------------------ launcher -------------------------------------
extern "C" void kernel_launch(void* const* d_in, const int* in_sizes, int n_in,
                              void* d_out, int out_size) {
    const float* x   = (const float*)d_in[0];
    const float* W3  = (const float*)d_in[1];
    const float* b3  = (const float*)d_in[2];
    const float* W4  = (const float*)d_in[3];
    const float* b4  = (const float*)d_in[4];
    const float* Wxf = (const float*)d_in[5];
    const float* Whf = (const float*)d_in[6];
    const float* bf  = (const float*)d_in[7];
    const float* Wxb = (const float*)d_in[8];
    const float* Whb = (const float*)d_in[9];
    const float* bb  = (const float*)d_in[10];
    const float* Wd  = (const float*)d_in[11];
    const float* bd  = (const float*)d_in[12];
    float* out = (float*)d_out;

    float *pf, *pxw0, *pxw1, *ph0, *ph1, *phbuf;
    cudaGetSymbolAddress((void**)&pf,    g_f);
    cudaGetSymbolAddress((void**)&pxw0,  g_xw0);
    cudaGetSymbolAddress((void**)&pxw1,  g_xw1);
    cudaGetSymbolAddress((void**)&ph0,   g_hseq0);
    cudaGetSymbolAddress((void**)&ph1,   g_hseq1);
    cudaGetSymbolAddress((void**)&phbuf, g_hbuf);

    cudaFuncSetAttribute(k_scan, cudaFuncAttributeMaxDynamicSharedMemorySize,
                         SCAN_SMEM);

    for (int it = 0; it < 2; ++it) {
        const float* hin = (it == 0) ? x : phbuf;
        float* hout = (it == 1) ? out : phbuf;

        // zp = (sum_a h[:, :, -1, :]/3) @ W4 + b4
        k_zzp<<<B_, D_>>>(hin, W4, b4);
        // f = tanh(h @ W3 + b3 + zp[b])
        k_gemm<0, 1, 256, 256><<<dim3(2, 512), 256>>>(hin, nullptr, W3, b3, pf);
        // gate input projections (fwd + time-reversed bwd)
        k_gemm<0, 0, 256, 1024><<<dim3(8, 512), 256>>>(pf, nullptr, Wxf, bf, pxw0);
        k_gemm<1, 0, 256, 1024><<<dim3(8, 512), 256>>>(pf, nullptr, Wxb, bb, pxw1);
        // cluster-local bidirectional LSTM scan (shuffle reduction)
        k_scan<<<32 * CL, 256, SCAN_SMEM>>>(Whf, Whb);
        // h = concat(hf, hb_rev) @ Wd + bd   (hseq in [t][n][j] layout)
        k_gemm<3, 0, 512, 256><<<dim3(2, 512), 256>>>(ph0, ph1, Wd, bd, hout);
    }
}

// round 13
// speedup vs baseline: 1.8372x; 1.8372x over previous
#include <cuda_runtime.h>
#include <cstddef>
#include <cstdint>

typedef unsigned long long ull;

// Problem constants
#define A_ 4
#define B_ 8
#define S_ 2048
#define D_ 256
#define N_ 32      // A_*B_
#define H_ 256
#define G_ 1024    // 4*H_
#define CL 8       // cluster size

// -------- scratch (device globals; allocation-free per harness rules) --------
__device__ float g_f[(size_t)N_ * S_ * D_];
__device__ float g_xw0[(size_t)N_ * S_ * G_];
__device__ float g_xw1[(size_t)N_ * S_ * G_];
__device__ float g_hseq0[(size_t)S_ * N_ * H_];   // [t][n][j] layout
__device__ float g_hseq1[(size_t)S_ * N_ * H_];   // [t][n][j] layout
__device__ float g_hbuf[(size_t)N_ * S_ * D_];
__device__ float g_zp[B_ * D_];

__device__ __forceinline__ float fsig(float x) { return 1.f / (1.f + __expf(-x)); }
__device__ __forceinline__ float ftanh(float x) {
    float t = __expf(-2.f * fabsf(x));
    float r = (1.f - t) / (1.f + t);
    return copysignf(r, x);
}
// fast approx versions for the scan recurrence (MUFU tanh, sm_75+)
__device__ __forceinline__ float tanh_fast(float x) {
    float y; asm("tanh.approx.f32 %0, %1;" : "=f"(y) : "f"(x)); return y;
}
__device__ __forceinline__ float sig_fast(float x) {
    return fmaf(tanh_fast(0.5f * x), 0.5f, 0.5f);
}

// f32x2 packed FFMA (sm_103a; only reachable via PTX)
#define FMA2(acc, a, b) asm("fma.rn.f32x2 %0, %1, %2, %0;" : "+l"(acc) : "l"(a), "l"(b))
#define PACK2(out, lo, hi) \
    asm("mov.b64 %0, {%1, %2};" : "=l"(out) : "f"(lo), "f"(hi))
#define UNPK(lo, hi, v)                                                      \
    do { unsigned _a, _b;                                                    \
         asm("mov.b64 {%0, %1}, %2;" : "=r"(_a), "=r"(_b) : "l"(v));         \
         lo = __uint_as_float(_a); hi = __uint_as_float(_b); } while (0)

__device__ __forceinline__ unsigned ctarank() {
    unsigned r; asm("mov.u32 %0, %%cluster_ctarank;" : "=r"(r)); return r;
}
__device__ __forceinline__ unsigned smem_u32(const void* p) {
    return (unsigned)__cvta_generic_to_shared(p);
}
__device__ __forceinline__ unsigned mapa_u32(unsigned a, unsigned rank) {
    unsigned r;
    asm("mapa.shared::cluster.u32 %0, %1, %2;" : "=r"(r) : "r"(a), "r"(rank));
    return r;
}
__device__ __forceinline__ void st_cluster_f32(unsigned a, float v) {
    asm volatile("st.shared::cluster.f32 [%0], %1;" :: "r"(a), "f"(v) : "memory");
}
__device__ __forceinline__ void mbar_init(unsigned a, unsigned cnt) {
    asm volatile("mbarrier.init.shared.b64 [%0], %1;" :: "r"(a), "r"(cnt) : "memory");
}
__device__ __forceinline__ void mbar_arrive_cluster(unsigned a) {
    asm volatile("mbarrier.arrive.release.cluster.shared::cluster.b64 _, [%0];"
                 :: "r"(a) : "memory");
}
__device__ __forceinline__ void mbar_wait_cluster(unsigned a, unsigned parity) {
    asm volatile(
        "{\n\t.reg .pred P;\n\t"
        "W%=:\n\t"
        "mbarrier.try_wait.parity.acquire.cluster.shared::cta.b64 P, [%0], %1, 0x989680;\n\t"
        "@!P bra W%=;\n\t}"
        :: "r"(a), "r"(parity) : "memory");
}

// ------------------------- z / zp (tiny matvec) ------------------------------
__global__ void k_zzp(const float* __restrict__ hin, const float* __restrict__ W4,
                      const float* __restrict__ b4) {
    __shared__ float zs[D_];
    int b = blockIdx.x;
    int e = threadIdx.x;
    float s = 0.f;
#pragma unroll
    for (int a = 0; a < A_; ++a)
        s += hin[(((size_t)(a * B_ + b)) * S_ + (S_ - 1)) * D_ + e];
    zs[e] = s * (1.f / 3.f);
    __syncthreads();
    float acc = b4[e];
#pragma unroll 8
    for (int d = 0; d < D_; ++d) acc += zs[d] * W4[d * D_ + e];
    g_zp[b * D_ + e] = acc;
}

// ------------------------- SGEMM (double-buffered) ---------------------------
// C[M x NDIM] = op(A)[M x KDIM] @ Bw[KDIM x NDIM] + bias (+ optional zp + tanh)
// AMODE 0: A0[m][k]
// AMODE 1: A0[(n, S-1-s)][k]          (time-reversed rows; m = n*S+s)
// AMODE 3: concat from [t][n][j] layout:
//          k<256 -> A0[(s*32+n)][k] ; k>=256 -> A1[((S-1-s)*32+n)][k-256]
// EPI 0: +bias   EPI 1: tanh(v + bias + g_zp[b])
template <int AMODE, int EPI, int KDIM, int NDIM>
__global__ void __launch_bounds__(256, 2)
k_gemm(const float* __restrict__ A0, const float* __restrict__ A1,
       const float* __restrict__ Bw, const float* __restrict__ bias,
       float* __restrict__ C) {
    __shared__ float As[2][8][128];
    __shared__ float Bs[2][8][128];
    const int tid = threadIdx.x;
    const int m0 = blockIdx.y * 128;
    const int n0 = blockIdx.x * 128;
    const int aRow = tid >> 1;
    const int aCol = (tid & 1) * 4;
    const int bRow = tid >> 5;
    const int bCol = (tid & 31) * 4;
    const int tr = (tid >> 4) * 8;
    const int tc = (tid & 15) * 8;

    const int m = m0 + aRow;
    const float* aP0;
    const float* aP1 = nullptr;
    if (AMODE == 0) {
        aP0 = A0 + (size_t)m * KDIM;
    } else if (AMODE == 1) {
        int n = m >> 11, s = m & 2047;
        aP0 = A0 + ((size_t)(n << 11) + (2047 - s)) * KDIM;
    } else {
        int n = m >> 11, s = m & 2047;
        aP0 = A0 + ((size_t)(s * 32) + n) * 256;
        aP1 = A1 + ((size_t)((2047 - s) * 32) + n) * 256;
    }
    const float* bP = Bw + (size_t)bRow * NDIM + n0 + bCol;

    float acc[8][8];
#pragma unroll
    for (int i = 0; i < 8; ++i)
#pragma unroll
        for (int j = 0; j < 8; ++j) acc[i][j] = 0.f;

    auto loadA = [&](int k0) -> float4 {
        if (AMODE != 3) {
            return *(const float4*)(aP0 + k0 + aCol);
        } else {
            int kk = k0 + aCol;
            return (kk < 256) ? *(const float4*)(aP0 + kk)
                              : *(const float4*)(aP1 + (kk - 256));
        }
    };
    auto loadB = [&](int k0) -> float4 {
        return *(const float4*)(bP + (size_t)k0 * NDIM);
    };

    constexpr int NT = KDIM / 8;

    {
        float4 av = loadA(0);
        float4 bv = loadB(0);
        As[0][aCol + 0][aRow] = av.x;
        As[0][aCol + 1][aRow] = av.y;
        As[0][aCol + 2][aRow] = av.z;
        As[0][aCol + 3][aRow] = av.w;
        *(float4*)&Bs[0][bRow][bCol] = bv;
    }
    __syncthreads();

    for (int t = 0; t < NT; ++t) {
        const int cur = t & 1;
        float4 av, bv;
        if (t + 1 < NT) {
            av = loadA((t + 1) * 8);
            bv = loadB((t + 1) * 8);
        }
#pragma unroll
        for (int kk = 0; kk < 8; ++kk) {
            float ra[8], rb[8];
            *(float4*)(ra)     = *(const float4*)&As[cur][kk][tr];
            *(float4*)(ra + 4) = *(const float4*)&As[cur][kk][tr + 4];
            *(float4*)(rb)     = *(const float4*)&Bs[cur][kk][tc];
            *(float4*)(rb + 4) = *(const float4*)&Bs[cur][kk][tc + 4];
#pragma unroll
            for (int i = 0; i < 8; ++i)
#pragma unroll
                for (int j = 0; j < 8; ++j) acc[i][j] += ra[i] * rb[j];
        }
        if (t + 1 < NT) {
            const int nxt = cur ^ 1;
            As[nxt][aCol + 0][aRow] = av.x;
            As[nxt][aCol + 1][aRow] = av.y;
            As[nxt][aCol + 2][aRow] = av.z;
            As[nxt][aCol + 3][aRow] = av.w;
            *(float4*)&Bs[nxt][bRow][bCol] = bv;
            __syncthreads();
        }
    }

#pragma unroll
    for (int i = 0; i < 8; ++i) {
        int mm = m0 + tr + i;
        float* crow = C + (size_t)mm * NDIM + n0 + tc;
        int bi = 0;
        if (EPI == 1) bi = (mm >> 11) & 7;
#pragma unroll
        for (int j4 = 0; j4 < 8; j4 += 4) {
            int col = n0 + tc + j4;
            float4 v = make_float4(acc[i][j4], acc[i][j4 + 1], acc[i][j4 + 2], acc[i][j4 + 3]);
            v.x += bias[col]; v.y += bias[col + 1]; v.z += bias[col + 2]; v.w += bias[col + 3];
            if (EPI == 1) {
                const float* zr = &g_zp[bi * D_];
                v.x = ftanh(v.x + zr[col]);     v.y = ftanh(v.y + zr[col + 1]);
                v.z = ftanh(v.z + zr[col + 2]); v.w = ftanh(v.w + zr[col + 3]);
            }
            *(float4*)(crow + j4) = v;
        }
    }
}

// ---- cluster LSTM scan: shuffle reduction, pair-barriers, 2 CTAs per SM -----
// Same structure as R12, with the smem weight layout fixed to be k-major
// (Ws[k2*256 + tid]) so lane addresses are consecutive -> conflict-free
// LDS.64 (R12's Ws[tid][k2] layout had a 256B thread stride = all lanes on
// the same bank group = 32-way conflicts; that was the whole regression).
// Thread map: tid = u*8 + gate*2 + kh. In-warp reduction via SHFL (kh = ^1,
// gate gather = ^2/^4), ONE __syncthreads per step, 4 pair-barrier waits
// (count=2: sources r and r+4 arrive on barrier r&3).
#define SCAN_SMEM (4096 + 64 + 65536)
__global__ void __launch_bounds__(256, 2) __cluster_dims__(CL, 1, 1)
k_scan(const float* __restrict__ Whf, const float* __restrict__ Whb) {
    extern __shared__ __align__(16) char smx[];
    float* hbuf = (float*)smx;              // [buf][s][unit] 2*2*256 = 4KB
    ull*   mbar = (ull*)(smx + 4096);       // [pair][buf] 4*2
    ull*   Ws   = (ull*)(smx + 4160);       // [k2][tid] 32*256 = 64KB

    const int tid = threadIdx.x;
    const unsigned rank = ctarank();
    const int cid = blockIdx.x >> 3;
    const int dir = cid >> 4;
    const int grp = cid & 15;
    const float* Wh   = dir ? Whb : Whf;
    const float* xw   = dir ? g_xw1 : g_xw0;
    float*       hseq = dir ? g_hseq1 : g_hseq0;
    const int ju0 = (int)rank * 32;

    const int kh   = tid & 1;
    const int gate = (tid >> 1) & 3;
    const int u    = tid >> 3;
    const int gcol = gate * 256 + ju0 + u;

    if (tid < 8)
        mbar_init(smem_u32(&mbar[0]) + (unsigned)tid * 8, 2);

    // ---- Wh slice: pairs 0..31 of this K-half in regs, 32..63 in smem ----
    ull W2[32];
#pragma unroll
    for (int k2 = 0; k2 < 32; ++k2) {
        const int k = kh * 128 + 2 * k2;
        float lo = __ldg(Wh + (size_t)k * G_ + gcol);
        float hi = __ldg(Wh + (size_t)(k + 1) * G_ + gcol);
        PACK2(W2[k2], lo, hi);
    }
    for (int k2 = 0; k2 < 32; ++k2) {
        const int k = kh * 128 + 2 * (32 + k2);
        float lo = __ldg(Wh + (size_t)k * G_ + gcol);
        float hi = __ldg(Wh + (size_t)(k + 1) * G_ + gcol);
        ull w; PACK2(w, lo, hi);
        Ws[k2 * 256 + tid] = w;            // k-major: lane-consecutive, no conflicts
    }
    __syncthreads();
    // barriers must be initialized cluster-wide before first arrive
    asm volatile("barrier.cluster.arrive.aligned;" ::: "memory");
    asm volatile("barrier.cluster.wait.aligned;" ::: "memory");

    // ---- push / arrive addresses ----
    unsigned pa[CL];
    {
        unsigned la = smem_u32(&hbuf[ju0 + u]);   // hbuf[0][0][ju0+u]
#pragma unroll
        for (unsigned r = 0; r < CL; ++r) pa[r] = mapa_u32(la, r);
    }
    unsigned amD = 0;
    if (tid < CL)
        amD = mapa_u32(smem_u32(&mbar[(rank & 3) * 2]), (unsigned)tid);
    const unsigned mb = smem_u32(&mbar[0]);
    const int nG0 = grp * 2;
    const float* xrow0 = xw + (size_t)nG0 * S_ * G_ + gcol;
    float creg0 = 0.f, creg1 = 0.f;

    for (int t = 0; t < S_; ++t) {
        const int buf = t & 1;

        // prefetch this step's input projections (own gate, both seqs)
        float x0 = __ldcg(xrow0 + (size_t)t * G_);
        float x1 = __ldcg(xrow0 + (size_t)(S_ + t) * G_);

        ull a0 = 0ull, a1 = 0ull;
        if (t > 0) {
            const unsigned par = (unsigned)(((t - 1) >> 1) & 1);
            const unsigned pb  = (unsigned)((t - 1) & 1);
            const float* hb = hbuf + (buf ^ 1) * 512 + kh * 128;
#define CHUNK(ci)                                                             \
            {                                                                 \
                mbar_wait_cluster(mb + ((ci) * 2 + pb) * 8, par);             \
                const float* hc = hb + (ci) * 32;                             \
                _Pragma("unroll")                                             \
                for (int q = 0; q < 4; ++q) {                                 \
                    const float* h0 = hc + q * 8;                             \
                    ulonglong2 A0 = *(const ulonglong2*)h0;                   \
                    ulonglong2 B0 = *(const ulonglong2*)(h0 + 4);             \
                    ulonglong2 A1v = *(const ulonglong2*)(h0 + 256);          \
                    ulonglong2 B1v = *(const ulonglong2*)(h0 + 260);          \
                    ull w0, w1, w2, w3;                                       \
                    if ((ci) < 2) {                                           \
                        w0 = W2[(ci) * 16 + q * 4 + 0];                       \
                        w1 = W2[(ci) * 16 + q * 4 + 1];                       \
                        w2 = W2[(ci) * 16 + q * 4 + 2];                       \
                        w3 = W2[(ci) * 16 + q * 4 + 3];                       \
                    } else {                                                  \
                        const ull* wp = Ws + (((ci) - 2) * 16 + q * 4) * 256  \
                                        + tid;                                \
                        w0 = wp[0];   w1 = wp[256];                           \
                        w2 = wp[512]; w3 = wp[768];                           \
                    }                                                         \
                    FMA2(a0, w0, A0.x); FMA2(a0, w1, A0.y);                   \
                    FMA2(a0, w2, B0.x); FMA2(a0, w3, B0.y);                   \
                    FMA2(a1, w0, A1v.x); FMA2(a1, w1, A1v.y);                 \
                    FMA2(a1, w2, B1v.x); FMA2(a1, w3, B1v.y);                 \
                }                                                             \
            }
            CHUNK(0) CHUNK(1) CHUNK(2) CHUNK(3)
#undef CHUNK
        }

        // ---- in-warp reduction: kh (lane^1), then gate gather (^2, ^4) ----
        float f0, f1;
        UNPK(f0, f1, a0); float g0 = f0 + f1;
        UNPK(f0, f1, a1); float g1 = f0 + f1;
        g0 += __shfl_xor_sync(0xffffffffu, g0, 1);
        g1 += __shfl_xor_sync(0xffffffffu, g1, 1);
        g0 += x0;
        g1 += x1;

        float t1 = __shfl_xor_sync(0xffffffffu, g0, 2);
        float ga = (gate & 1) ? t1 : g0;
        float gb = (gate & 1) ? g0 : t1;
        float t2 = __shfl_xor_sync(0xffffffffu, ga, 4);
        float t3 = __shfl_xor_sync(0xffffffffu, gb, 4);
        float qi0 = (gate < 2) ? ga : t2;
        float qf0 = (gate < 2) ? gb : t3;
        float qg0 = (gate < 2) ? t2 : ga;
        float qo0 = (gate < 2) ? t3 : gb;

        t1 = __shfl_xor_sync(0xffffffffu, g1, 2);
        ga = (gate & 1) ? t1 : g1;
        gb = (gate & 1) ? g1 : t1;
        t2 = __shfl_xor_sync(0xffffffffu, ga, 4);
        t3 = __shfl_xor_sync(0xffffffffu, gb, 4);
        float qi1 = (gate < 2) ? ga : t2;
        float qf1 = (gate < 2) ? gb : t3;
        float qg1 = (gate < 2) ? t2 : ga;
        float qo1 = (gate < 2) ? t3 : gb;

        if ((tid & 7) == 0) {
            float ii = sig_fast(qi0), ff = sig_fast(qf0);
            float gg = tanh_fast(qg0), oo = sig_fast(qo0);
            creg0 = ff * creg0 + ii * gg;
            float hv0 = oo * tanh_fast(creg0);

            ii = sig_fast(qi1); ff = sig_fast(qf1);
            gg = tanh_fast(qg1); oo = sig_fast(qo1);
            creg1 = ff * creg1 + ii * gg;
            float hv1 = oo * tanh_fast(creg1);

            float* hs = &hseq[((size_t)t * N_ + nG0) * H_ + ju0 + u];
            __stcg(hs, hv0);
            __stcg(hs + H_, hv1);
            if (t < S_ - 1) {
                const unsigned boff = (unsigned)buf << 11;   // buf*2048 bytes
#pragma unroll
                for (int r = 0; r < CL; ++r) {
                    st_cluster_f32(pa[r] + boff, hv0);
                    st_cluster_f32(pa[r] + boff + 1024u, hv1);
                }
            }
        }
        __syncthreads();   // all pushes ordered before the release-arrives
        if (t < S_ - 1 && tid < CL)
            mbar_arrive_cluster(amD + (unsigned)buf * 8);
    }

    if (tid == 0) {
#pragma unroll
        for (int i = 0; i < 8; ++i)
            asm volatile("mbarrier.inval.shared.b64 [%0];"
                         :: "r"(smem_u32(&mbar[0]) + i * 8) : "memory");
    }
    // no CTA may exit while peers might still push into its smem
    asm volatile("barrier.cluster.arrive.aligned;" ::: "memory");
    asm volatile("barrier.cluster.wait.aligned;" ::: "memory");
}

// ------------------------------ launcher -------------------------------------
extern "C" void kernel_launch(void* const* d_in, const int* in_sizes, int n_in,
                              void* d_out, int out_size) {
    const float* x   = (const float*)d_in[0];
    const float* W3  = (const float*)d_in[1];
    const float* b3  = (const float*)d_in[2];
    const float* W4  = (const float*)d_in[3];
    const float* b4  = (const float*)d_in[4];
    const float* Wxf = (const float*)d_in[5];
    const float* Whf = (const float*)d_in[6];
    const float* bf  = (const float*)d_in[7];
    const float* Wxb = (const float*)d_in[8];
    const float* Whb = (const float*)d_in[9];
    const float* bb  = (const float*)d_in[10];
    const float* Wd  = (const float*)d_in[11];
    const float* bd  = (const float*)d_in[12];
    float* out = (float*)d_out;

    float *pf, *pxw0, *pxw1, *ph0, *ph1, *phbuf;
    cudaGetSymbolAddress((void**)&pf,    g_f);
    cudaGetSymbolAddress((void**)&pxw0,  g_xw0);
    cudaGetSymbolAddress((void**)&pxw1,  g_xw1);
    cudaGetSymbolAddress((void**)&ph0,   g_hseq0);
    cudaGetSymbolAddress((void**)&ph1,   g_hseq1);
    cudaGetSymbolAddress((void**)&phbuf, g_hbuf);

    cudaFuncSetAttribute(k_scan, cudaFuncAttributeMaxDynamicSharedMemorySize,
                         SCAN_SMEM);

    for (int it = 0; it < 2; ++it) {
        const float* hin = (it == 0) ? x : phbuf;
        float* hout = (it == 1) ? out : phbuf;

        // zp = (sum_a h[:, :, -1, :]/3) @ W4 + b4
        k_zzp<<<B_, D_>>>(hin, W4, b4);
        // f = tanh(h @ W3 + b3 + zp[b])
        k_gemm<0, 1, 256, 256><<<dim3(2, 512), 256>>>(hin, nullptr, W3, b3, pf);
        // gate input projections (fwd + time-reversed bwd)
        k_gemm<0, 0, 256, 1024><<<dim3(8, 512), 256>>>(pf, nullptr, Wxf, bf, pxw0);
        k_gemm<1, 0, 256, 1024><<<dim3(8, 512), 256>>>(pf, nullptr, Wxb, bb, pxw1);
        // cluster-local bidirectional LSTM scan (shuffle reduction, fixed Ws)
        k_scan<<<32 * CL, 256, SCAN_SMEM>>>(Whf, Whb);
        // h = concat(hf, hb_rev) @ Wd + bd   (hseq in [t][n][j] layout)
        k_gemm<3, 0, 512, 256><<<dim3(2, 512), 256>>>(ph0, ph1, Wd, bd, hout);
    }
}

// round 14
// speedup vs baseline: 2.6214x; 1.4269x over previous
#include <cuda_runtime.h>
#include <cstddef>
#include <cstdint>

typedef unsigned long long ull;

// Problem constants
#define A_ 4
#define B_ 8
#define S_ 2048
#define D_ 256
#define N_ 32      // A_*B_
#define H_ 256
#define G_ 1024    // 4*H_
#define CL 8       // cluster size

// -------- scratch (device globals; allocation-free per harness rules) --------
__device__ float g_f[(size_t)N_ * S_ * D_];
__device__ float g_xw0[(size_t)N_ * S_ * G_];
__device__ float g_xw1[(size_t)N_ * S_ * G_];
__device__ float g_hseq0[(size_t)S_ * N_ * H_];   // [t][n][j] layout
__device__ float g_hseq1[(size_t)S_ * N_ * H_];   // [t][n][j] layout
__device__ float g_hbuf[(size_t)N_ * S_ * D_];
__device__ float g_zp[B_ * D_];

__device__ __forceinline__ float fsig(float x) { return 1.f / (1.f + __expf(-x)); }
__device__ __forceinline__ float ftanh(float x) {
    float t = __expf(-2.f * fabsf(x));
    float r = (1.f - t) / (1.f + t);
    return copysignf(r, x);
}
// fast approx versions for the scan recurrence (MUFU tanh, sm_75+)
__device__ __forceinline__ float tanh_fast(float x) {
    float y; asm("tanh.approx.f32 %0, %1;" : "=f"(y) : "f"(x)); return y;
}
__device__ __forceinline__ float sig_fast(float x) {
    return fmaf(tanh_fast(0.5f * x), 0.5f, 0.5f);
}

// f32x2 packed FFMA (sm_103a; only reachable via PTX)
#define FMA2(acc, a, b) asm("fma.rn.f32x2 %0, %1, %2, %0;" : "+l"(acc) : "l"(a), "l"(b))
#define PACK2(out, lo, hi) \
    asm("mov.b64 %0, {%1, %2};" : "=l"(out) : "f"(lo), "f"(hi))
#define UNPK(lo, hi, v)                                                      \
    do { unsigned _a, _b;                                                    \
         asm("mov.b64 {%0, %1}, %2;" : "=r"(_a), "=r"(_b) : "l"(v));         \
         lo = __uint_as_float(_a); hi = __uint_as_float(_b); } while (0)

__device__ __forceinline__ unsigned ctarank() {
    unsigned r; asm("mov.u32 %0, %%cluster_ctarank;" : "=r"(r)); return r;
}
__device__ __forceinline__ unsigned smem_u32(const void* p) {
    return (unsigned)__cvta_generic_to_shared(p);
}
__device__ __forceinline__ unsigned mapa_u32(unsigned a, unsigned rank) {
    unsigned r;
    asm("mapa.shared::cluster.u32 %0, %1, %2;" : "=r"(r) : "r"(a), "r"(rank));
    return r;
}
__device__ __forceinline__ void st_cluster_f32(unsigned a, float v) {
    asm volatile("st.shared::cluster.f32 [%0], %1;" :: "r"(a), "f"(v) : "memory");
}
__device__ __forceinline__ void mbar_init(unsigned a, unsigned cnt) {
    asm volatile("mbarrier.init.shared.b64 [%0], %1;" :: "r"(a), "r"(cnt) : "memory");
}
__device__ __forceinline__ void mbar_arrive_cluster(unsigned a) {
    asm volatile("mbarrier.arrive.release.cluster.shared::cluster.b64 _, [%0];"
                 :: "r"(a) : "memory");
}
__device__ __forceinline__ void mbar_wait_cluster(unsigned a, unsigned parity) {
    asm volatile(
        "{\n\t.reg .pred P;\n\t"
        "W%=:\n\t"
        "mbarrier.try_wait.parity.acquire.cluster.shared::cta.b64 P, [%0], %1, 0x989680;\n\t"
        "@!P bra W%=;\n\t}"
        :: "r"(a), "r"(parity) : "memory");
}
// 16-byte async global->shared copy (LDGSTS)
__device__ __forceinline__ void cp16(unsigned dst, const void* src) {
    asm volatile("cp.async.cg.shared.global [%0], [%1], 16;"
                 :: "r"(dst), "l"(src) : "memory");
}
#define CP_COMMIT() asm volatile("cp.async.commit_group;" ::: "memory")
#define CP_WAIT0()  asm volatile("cp.async.wait_group 0;" ::: "memory")

// ------------------------- z / zp (tiny matvec) ------------------------------
__global__ void k_zzp(const float* __restrict__ hin, const float* __restrict__ W4,
                      const float* __restrict__ b4) {
    __shared__ float zs[D_];
    int b = blockIdx.x;
    int e = threadIdx.x;
    float s = 0.f;
#pragma unroll
    for (int a = 0; a < A_; ++a)
        s += hin[(((size_t)(a * B_ + b)) * S_ + (S_ - 1)) * D_ + e];
    zs[e] = s * (1.f / 3.f);
    __syncthreads();
    float acc = b4[e];
#pragma unroll 8
    for (int d = 0; d < D_; ++d) acc += zs[d] * W4[d * D_ + e];
    g_zp[b * D_ + e] = acc;
}

// ---------------- SGEMM (double-buffered, cp.async B tiles) ------------------
// C[M x NDIM] = op(A)[M x KDIM] @ Bw[KDIM x NDIM] + bias (+ optional zp + tanh)
// AMODE 0: A0[m][k]
// AMODE 1: A0[(n, S-1-s)][k]          (time-reversed rows; m = n*S+s)
// AMODE 3: concat from [t][n][j] layout:
//          k<256 -> A0[(s*32+n)][k] ; k>=256 -> A1[((S-1-s)*32+n)][k-256]
// EPI 0: +bias   EPI 1: tanh(v + bias + g_zp[b])
// A staged via LDG+STS (needs transpose); B copied with cp.async (no
// transpose) so its fetch fully overlaps the FFMA block. One BAR per tile.
template <int AMODE, int EPI, int KDIM, int NDIM>
__global__ void __launch_bounds__(256, 2)
k_gemm(const float* __restrict__ A0, const float* __restrict__ A1,
       const float* __restrict__ Bw, const float* __restrict__ bias,
       float* __restrict__ C) {
    __shared__ float As[2][8][128];
    __shared__ float Bs[2][8][128];
    const int tid = threadIdx.x;
    const int m0 = blockIdx.y * 128;
    const int n0 = blockIdx.x * 128;
    const int aRow = tid >> 1;
    const int aCol = (tid & 1) * 4;
    const int bRow = tid >> 5;
    const int bCol = (tid & 31) * 4;
    const int tr = (tid >> 4) * 8;
    const int tc = (tid & 15) * 8;

    const int m = m0 + aRow;
    const float* aP0;
    const float* aP1 = nullptr;
    if (AMODE == 0) {
        aP0 = A0 + (size_t)m * KDIM;
    } else if (AMODE == 1) {
        int n = m >> 11, s = m & 2047;
        aP0 = A0 + ((size_t)(n << 11) + (2047 - s)) * KDIM;
    } else {
        int n = m >> 11, s = m & 2047;
        aP0 = A0 + ((size_t)(s * 32) + n) * 256;
        aP1 = A1 + ((size_t)((2047 - s) * 32) + n) * 256;
    }
    const float* bP = Bw + (size_t)bRow * NDIM + n0 + bCol;
    const unsigned bDst0 = smem_u32(&Bs[0][bRow][bCol]);
    const unsigned bDst1 = smem_u32(&Bs[1][bRow][bCol]);

    float acc[8][8];
#pragma unroll
    for (int i = 0; i < 8; ++i)
#pragma unroll
        for (int j = 0; j < 8; ++j) acc[i][j] = 0.f;

    auto loadA = [&](int k0) -> float4 {
        if (AMODE != 3) {
            return *(const float4*)(aP0 + k0 + aCol);
        } else {
            int kk = k0 + aCol;
            return (kk < 256) ? *(const float4*)(aP0 + kk)
                              : *(const float4*)(aP1 + (kk - 256));
        }
    };

    constexpr int NT = KDIM / 8;

    // prologue: tile 0 -> buffer 0 (A via LDG+STS, B via cp.async)
    {
        float4 av = loadA(0);
        cp16(bDst0, bP);
        CP_COMMIT();
        As[0][aCol + 0][aRow] = av.x;
        As[0][aCol + 1][aRow] = av.y;
        As[0][aCol + 2][aRow] = av.z;
        As[0][aCol + 3][aRow] = av.w;
        CP_WAIT0();
    }
    __syncthreads();

    for (int t = 0; t < NT; ++t) {
        const int cur = t & 1;
        float4 av;
        if (t + 1 < NT) {
            // next B straight into the other smem buffer (overlaps compute)
            cp16(cur ? bDst0 : bDst1, bP + (size_t)((t + 1) * 8) * NDIM);
            CP_COMMIT();
            av = loadA((t + 1) * 8);
        }
#pragma unroll
        for (int kk = 0; kk < 8; ++kk) {
            float ra[8], rb[8];
            *(float4*)(ra)     = *(const float4*)&As[cur][kk][tr];
            *(float4*)(ra + 4) = *(const float4*)&As[cur][kk][tr + 4];
            *(float4*)(rb)     = *(const float4*)&Bs[cur][kk][tc];
            *(float4*)(rb + 4) = *(const float4*)&Bs[cur][kk][tc + 4];
#pragma unroll
            for (int i = 0; i < 8; ++i)
#pragma unroll
                for (int j = 0; j < 8; ++j) acc[i][j] += ra[i] * rb[j];
        }
        if (t + 1 < NT) {
            const int nxt = cur ^ 1;
            As[nxt][aCol + 0][aRow] = av.x;
            As[nxt][aCol + 1][aRow] = av.y;
            As[nxt][aCol + 2][aRow] = av.z;
            As[nxt][aCol + 3][aRow] = av.w;
            CP_WAIT0();
            __syncthreads();
        }
    }

#pragma unroll
    for (int i = 0; i < 8; ++i) {
        int mm = m0 + tr + i;
        float* crow = C + (size_t)mm * NDIM + n0 + tc;
        int bi = 0;
        if (EPI == 1) bi = (mm >> 11) & 7;
#pragma unroll
        for (int j4 = 0; j4 < 8; j4 += 4) {
            int col = n0 + tc + j4;
            float4 v = make_float4(acc[i][j4], acc[i][j4 + 1], acc[i][j4 + 2], acc[i][j4 + 3]);
            v.x += bias[col]; v.y += bias[col + 1]; v.z += bias[col + 2]; v.w += bias[col + 3];
            if (EPI == 1) {
                const float* zr = &g_zp[bi * D_];
                v.x = ftanh(v.x + zr[col]);     v.y = ftanh(v.y + zr[col + 1]);
                v.z = ftanh(v.z + zr[col + 2]); v.w = ftanh(v.w + zr[col + 3]);
            }
            *(float4*)(crow + j4) = v;
        }
    }
}

// -------- cluster LSTM scan (R11 proven version, verbatim) -------------------
// 32 clusters x 8 CTAs. Cluster c: dir = c>>4, grp = c&15 -> seqs {2grp,2grp+1}.
// CTA rank r owns hidden units [32r, 32r+32). Wh slice: K-pairs 0..31 of each
// thread's K-half in REGISTERS, pairs 32..63 in SMEM (64KB, [kp][c] layout =
// lane-consecutive, conflict-free). 2 CTAs per SM hide sync/DSMEM latency.
// Per-source chunked mbarrier waits (R8 pattern).
#define SCAN_SMEM (4096 + 4096 + 128 + 65536)
__global__ void __launch_bounds__(256, 2) __cluster_dims__(CL, 1, 1)
k_scan(const float* __restrict__ Whf, const float* __restrict__ Whb) {
    extern __shared__ __align__(16) char smx[];
    float* hbuf = (float*)smx;                 // [buf][s][k]  2*2*256 = 4KB
    ull*   red  = (ull*)(smx + 4096);          // [kh][gate][s][u] 2*4*2*32 = 4KB
    ull*   mbar = (ull*)(smx + 8192);          // [src][buf] 8*2
    ull*   Ws   = (ull*)(smx + 8320);          // [kh][kp2][c] 2*32*128 = 64KB

    const int tid = threadIdx.x;
    const unsigned rank = ctarank();
    const int cid = blockIdx.x >> 3;
    const int dir = cid >> 4;
    const int grp = cid & 15;
    const float* Wh   = dir ? Whb : Whf;
    const float* xw   = dir ? g_xw1 : g_xw0;
    float*       hseq = dir ? g_hseq1 : g_hseq0;
    const int ju0 = (int)rank * 32;

    if (tid < 16)
        mbar_init(smem_u32(&mbar[0]) + (unsigned)tid * 8, 1);

    // ---- Wh slice: regs (k-pairs 0..31 of the K-half) + smem (32..63) ----
    const int kh   = tid >> 7;        // K half (warp-uniform)
    const int c    = tid & 127;       // gate*32 + unit
    const int gate = c >> 5;
    const int u    = c & 31;
    const int gcol = gate * 256 + ju0 + u;
    ull W2[32];
#pragma unroll
    for (int k2 = 0; k2 < 32; ++k2) {
        const int k = kh * 128 + 2 * k2;
        float lo = __ldg(Wh + (size_t)k * G_ + gcol);
        float hi = __ldg(Wh + (size_t)(k + 1) * G_ + gcol);
        PACK2(W2[k2], lo, hi);
    }
    for (int k2 = 0; k2 < 32; ++k2) {
        const int k = kh * 128 + 2 * (32 + k2);
        float lo = __ldg(Wh + (size_t)k * G_ + gcol);
        float hi = __ldg(Wh + (size_t)(k + 1) * G_ + gcol);
        ull w; PACK2(w, lo, hi);
        Ws[(kh * 32 + k2) * 128 + c] = w;
    }
    __syncthreads();
    // mbarriers must be initialized cluster-wide before first arrive
    asm volatile("barrier.cluster.arrive.aligned;" ::: "memory");
    asm volatile("barrier.cluster.wait.aligned;" ::: "memory");

    // ---- epilogue roles (tid<64): es = seq (0/1), ue = unit ----
    const int es = tid >> 5;
    const int ue = tid & 31;
    unsigned pa[CL];
    if (tid < 64) {
        unsigned la = smem_u32(&hbuf[es * 256 + ju0 + ue]);
#pragma unroll
        for (unsigned r = 0; r < CL; ++r) pa[r] = mapa_u32(la, r);
    }
    // thread tid<8 arrives at destination CTA 'tid' on barrier mbar[rank][buf]
    unsigned amD = 0;
    if (tid < CL)
        amD = mapa_u32(smem_u32(&mbar[rank * 2]), (unsigned)tid);
    const int nG = grp * 2 + es;      // global sequence (tid<64)
    float creg = 0.f;

    for (int t = 0; t < S_; ++t) {
        const int buf = t & 1;

        // prefetch this step's input projections (overlaps waits + GEMM)
        float xi = 0.f, xf = 0.f, xg = 0.f, xo = 0.f;
        if (tid < 64) {
            const float* xp = xw + ((size_t)nG * S_ + t) * G_ + ju0 + ue;
            xi = __ldcg(xp);
            xf = __ldcg(xp + 256);
            xg = __ldcg(xp + 512);
            xo = __ldcg(xp + 768);
        }

        ull a0 = 0ull, a1 = 0ull;     // 2 seqs
        if (t > 0) {
            const unsigned par = (unsigned)(((t - 1) >> 1) & 1);
            const unsigned pb  = (unsigned)((t - 1) & 1);
            const float* hball = hbuf + (buf ^ 1) * 512;
            // 4 source chunks of this K-half; wait per chunk before consuming
#pragma unroll
            for (int ci = 0; ci < 4; ++ci) {
                const int src = kh * 4 + ci;
                mbar_wait_cluster(smem_u32(&mbar[src * 2]) + pb * 8, par);
                const float* hb = hball + src * 32;
#pragma unroll
                for (int q = 0; q < 4; ++q) {       // 8 K-values per q
                    ulonglong2 hA0 = *(const ulonglong2*)(hb + q * 8);
                    ulonglong2 hB0 = *(const ulonglong2*)(hb + q * 8 + 4);
                    ulonglong2 hA1 = *(const ulonglong2*)(hb + 256 + q * 8);
                    ulonglong2 hB1 = *(const ulonglong2*)(hb + 256 + q * 8 + 4);
                    ull w0, w1, w2, w3;
                    if (ci < 2) {
                        const int kp = ci * 16 + q * 4;
                        w0 = W2[kp]; w1 = W2[kp + 1]; w2 = W2[kp + 2]; w3 = W2[kp + 3];
                    } else {
                        const ull* wsm = Ws + (kh * 32 + (ci - 2) * 16 + q * 4) * 128 + c;
                        w0 = wsm[0]; w1 = wsm[128]; w2 = wsm[256]; w3 = wsm[384];
                    }
                    FMA2(a0, w0, hA0.x); FMA2(a0, w1, hA0.y);
                    FMA2(a0, w2, hB0.x); FMA2(a0, w3, hB0.y);
                    FMA2(a1, w0, hA1.x); FMA2(a1, w1, hA1.y);
                    FMA2(a1, w2, hB1.x); FMA2(a1, w3, hB1.y);
                }
            }
        }
        red[((kh * 4 + gate) * 2 + 0) * 32 + u] = a0;
        red[((kh * 4 + gate) * 2 + 1) * 32 + u] = a1;
        __syncthreads();

        if (tid < 64) {
            float v[4];
#pragma unroll
            for (int g = 0; g < 4; ++g) {
                float q0, q1, q2, q3;
                UNPK(q0, q1, red[((0 + g) * 2 + es) * 32 + ue]);
                UNPK(q2, q3, red[((4 + g) * 2 + es) * 32 + ue]);
                v[g] = (q0 + q1) + (q2 + q3);
            }
            float gi = v[0] + xi, gf = v[1] + xf, gg = v[2] + xg, go = v[3] + xo;
            float ii = sig_fast(gi), ff = sig_fast(gf);
            float g2 = tanh_fast(gg), oo = sig_fast(go);
            creg = ff * creg + ii * g2;
            float hv = oo * tanh_fast(creg);
            if (t < S_ - 1) {
                const unsigned boff = (unsigned)buf << 11;   // buf*2048 bytes
#pragma unroll
                for (int r = 0; r < CL; ++r) st_cluster_f32(pa[r] + boff, hv);
            }
            __stcg(&hseq[((size_t)t * N_ + nG) * H_ + ju0 + ue], hv);
        }
        __syncthreads();   // all pushes ordered before the release-arrives
        if (t < S_ - 1 && tid < CL)
            mbar_arrive_cluster(amD + (unsigned)buf * 8);
    }

    if (tid == 0) {
#pragma unroll
        for (int i = 0; i < 16; ++i)
            asm volatile("mbarrier.inval.shared.b64 [%0];"
                         :: "r"(smem_u32(&mbar[0]) + i * 8) : "memory");
    }
    // no CTA may exit while peers might still push into its smem
    asm volatile("barrier.cluster.arrive.aligned;" ::: "memory");
    asm volatile("barrier.cluster.wait.aligned;" ::: "memory");
}

// ------------------------------ launcher -------------------------------------
extern "C" void kernel_launch(void* const* d_in, const int* in_sizes, int n_in,
                              void* d_out, int out_size) {
    const float* x   = (const float*)d_in[0];
    const float* W3  = (const float*)d_in[1];
    const float* b3  = (const float*)d_in[2];
    const float* W4  = (const float*)d_in[3];
    const float* b4  = (const float*)d_in[4];
    const float* Wxf = (const float*)d_in[5];
    const float* Whf = (const float*)d_in[6];
    const float* bf  = (const float*)d_in[7];
    const float* Wxb = (const float*)d_in[8];
    const float* Whb = (const float*)d_in[9];
    const float* bb  = (const float*)d_in[10];
    const float* Wd  = (const float*)d_in[11];
    const float* bd  = (const float*)d_in[12];
    float* out = (float*)d_out;

    float *pf, *pxw0, *pxw1, *ph0, *ph1, *phbuf;
    cudaGetSymbolAddress((void**)&pf,    g_f);
    cudaGetSymbolAddress((void**)&pxw0,  g_xw0);
    cudaGetSymbolAddress((void**)&pxw1,  g_xw1);
    cudaGetSymbolAddress((void**)&ph0,   g_hseq0);
    cudaGetSymbolAddress((void**)&ph1,   g_hseq1);
    cudaGetSymbolAddress((void**)&phbuf, g_hbuf);

    cudaFuncSetAttribute(k_scan, cudaFuncAttributeMaxDynamicSharedMemorySize,
                         SCAN_SMEM);

    for (int it = 0; it < 2; ++it) {
        const float* hin = (it == 0) ? x : phbuf;
        float* hout = (it == 1) ? out : phbuf;

        // zp = (sum_a h[:, :, -1, :]/3) @ W4 + b4
        k_zzp<<<B_, D_>>>(hin, W4, b4);
        // f = tanh(h @ W3 + b3 + zp[b])
        k_gemm<0, 1, 256, 256><<<dim3(2, 512), 256>>>(hin, nullptr, W3, b3, pf);
        // gate input projections (fwd + time-reversed bwd)
        k_gemm<0, 0, 256, 1024><<<dim3(8, 512), 256>>>(pf, nullptr, Wxf, bf, pxw0);
        k_gemm<1, 0, 256, 1024><<<dim3(8, 512), 256>>>(pf, nullptr, Wxb, bb, pxw1);
        // cluster-local bidirectional LSTM scan (R11 proven version)
        k_scan<<<32 * CL, 256, SCAN_SMEM>>>(Whf, Whb);
        // h = concat(hf, hb_rev) @ Wd + bd   (hseq in [t][n][j] layout)
        k_gemm<3, 0, 512, 256><<<dim3(2, 512), 256>>>(ph0, ph1, Wd, bd, hout);
    }
}

// round 15
// speedup vs baseline: 2.6275x; 1.0023x over previous
#include <cuda_runtime.h>
#include <cstddef>
#include <cstdint>

typedef unsigned long long ull;

// Problem constants
#define A_ 4
#define B_ 8
#define S_ 2048
#define D_ 256
#define N_ 32      // A_*B_
#define H_ 256
#define G_ 1024    // 4*H_
#define CL 8       // cluster size

// -------- scratch (device globals; allocation-free per harness rules) --------
__device__ float g_f[(size_t)N_ * S_ * D_];
__device__ float g_xw0[(size_t)N_ * S_ * G_];
__device__ float g_xw1[(size_t)N_ * S_ * G_];
__device__ float g_hseq0[(size_t)S_ * N_ * H_];   // [t][n][j] layout
__device__ float g_hseq1[(size_t)S_ * N_ * H_];   // [t][n][j] layout
__device__ float g_hbuf[(size_t)N_ * S_ * D_];
__device__ float g_zp[B_ * D_];

__device__ __forceinline__ float fsig(float x) { return 1.f / (1.f + __expf(-x)); }
__device__ __forceinline__ float ftanh(float x) {
    float t = __expf(-2.f * fabsf(x));
    float r = (1.f - t) / (1.f + t);
    return copysignf(r, x);
}
// fast approx versions for the scan recurrence (MUFU tanh, sm_75+)
__device__ __forceinline__ float tanh_fast(float x) {
    float y; asm("tanh.approx.f32 %0, %1;" : "=f"(y) : "f"(x)); return y;
}
__device__ __forceinline__ float sig_fast(float x) {
    return fmaf(tanh_fast(0.5f * x), 0.5f, 0.5f);
}

// f32x2 packed FFMA (sm_103a; only reachable via PTX)
#define FMA2(acc, a, b) asm("fma.rn.f32x2 %0, %1, %2, %0;" : "+l"(acc) : "l"(a), "l"(b))
#define PACK2(out, lo, hi) \
    asm("mov.b64 %0, {%1, %2};" : "=l"(out) : "f"(lo), "f"(hi))
#define UNPK(lo, hi, v)                                                      \
    do { unsigned _a, _b;                                                    \
         asm("mov.b64 {%0, %1}, %2;" : "=r"(_a), "=r"(_b) : "l"(v));         \
         lo = __uint_as_float(_a); hi = __uint_as_float(_b); } while (0)

__device__ __forceinline__ unsigned ctarank() {
    unsigned r; asm("mov.u32 %0, %%cluster_ctarank;" : "=r"(r)); return r;
}
__device__ __forceinline__ unsigned smem_u32(const void* p) {
    return (unsigned)__cvta_generic_to_shared(p);
}
__device__ __forceinline__ unsigned mapa_u32(unsigned a, unsigned rank) {
    unsigned r;
    asm("mapa.shared::cluster.u32 %0, %1, %2;" : "=r"(r) : "r"(a), "r"(rank));
    return r;
}
__device__ __forceinline__ void st_cluster_f32(unsigned a, float v) {
    asm volatile("st.shared::cluster.f32 [%0], %1;" :: "r"(a), "f"(v) : "memory");
}
__device__ __forceinline__ void mbar_init(unsigned a, unsigned cnt) {
    asm volatile("mbarrier.init.shared.b64 [%0], %1;" :: "r"(a), "r"(cnt) : "memory");
}
__device__ __forceinline__ void mbar_arrive_cluster(unsigned a) {
    asm volatile("mbarrier.arrive.release.cluster.shared::cluster.b64 _, [%0];"
                 :: "r"(a) : "memory");
}
__device__ __forceinline__ void mbar_wait_cluster(unsigned a, unsigned parity) {
    asm volatile(
        "{\n\t.reg .pred P;\n\t"
        "W%=:\n\t"
        "mbarrier.try_wait.parity.acquire.cluster.shared::cta.b64 P, [%0], %1, 0x989680;\n\t"
        "@!P bra W%=;\n\t}"
        :: "r"(a), "r"(parity) : "memory");
}
// 16-byte async global->shared copy (LDGSTS)
__device__ __forceinline__ void cp16(unsigned dst, const void* src) {
    asm volatile("cp.async.cg.shared.global [%0], [%1], 16;"
                 :: "r"(dst), "l"(src) : "memory");
}
#define CP_COMMIT() asm volatile("cp.async.commit_group;" ::: "memory")
#define CP_WAIT1()  asm volatile("cp.async.wait_group 1;" ::: "memory")

// ------------------------- z / zp (tiny matvec) ------------------------------
__global__ void k_zzp(const float* __restrict__ hin, const float* __restrict__ W4,
                      const float* __restrict__ b4) {
    __shared__ float zs[D_];
    int b = blockIdx.x;
    int e = threadIdx.x;
    float s = 0.f;
#pragma unroll
    for (int a = 0; a < A_; ++a)
        s += hin[(((size_t)(a * B_ + b)) * S_ + (S_ - 1)) * D_ + e];
    zs[e] = s * (1.f / 3.f);
    __syncthreads();
    float acc = b4[e];
#pragma unroll 8
    for (int d = 0; d < D_; ++d) acc += zs[d] * W4[d * D_ + e];
    g_zp[b * D_ + e] = acc;
}

// ------- SGEMM (3-buffer, cp.async B at prefetch distance 2) -----------------
// C[M x NDIM] = op(A)[M x KDIM] @ Bw[KDIM x NDIM] + bias (+ optional zp + tanh)
// AMODE 0: A0[m][k]
// AMODE 1: A0[(n, S-1-s)][k]          (time-reversed rows; m = n*S+s)
// AMODE 3: concat from [t][n][j] layout:
//          k<256 -> A0[(s*32+n)][k] ; k>=256 -> A1[((S-1-s)*32+n)][k-256]
// EPI 0: +bias   EPI 1: tanh(v + bias + g_zp[b])
// B: cp.async with 3 smem buffers, commit B(t+2) at top of iter t, wait_group 1
// at the bottom -> B(t+1) resident, B(t+2) still in flight (true distance-2
// pipelining; R14's wait_group 0 serialized it). A: LDG->reg->STS distance 1
// (needs in-register transpose). One __syncthreads per tile.
template <int AMODE, int EPI, int KDIM, int NDIM>
__global__ void __launch_bounds__(256, 2)
k_gemm(const float* __restrict__ A0, const float* __restrict__ A1,
       const float* __restrict__ Bw, const float* __restrict__ bias,
       float* __restrict__ C) {
    __shared__ float As[3][8][128];
    __shared__ float Bs[3][8][128];
    const int tid = threadIdx.x;
    const int m0 = blockIdx.y * 128;
    const int n0 = blockIdx.x * 128;
    const int aRow = tid >> 1;
    const int aCol = (tid & 1) * 4;
    const int bRow = tid >> 5;
    const int bCol = (tid & 31) * 4;
    const int tr = (tid >> 4) * 8;
    const int tc = (tid & 15) * 8;

    const int m = m0 + aRow;
    const float* aP0;
    const float* aP1 = nullptr;
    if (AMODE == 0) {
        aP0 = A0 + (size_t)m * KDIM;
    } else if (AMODE == 1) {
        int n = m >> 11, s = m & 2047;
        aP0 = A0 + ((size_t)(n << 11) + (2047 - s)) * KDIM;
    } else {
        int n = m >> 11, s = m & 2047;
        aP0 = A0 + ((size_t)(s * 32) + n) * 256;
        aP1 = A1 + ((size_t)((2047 - s) * 32) + n) * 256;
    }
    const float* bP = Bw + (size_t)bRow * NDIM + n0 + bCol;
    unsigned bDst[3];
    bDst[0] = smem_u32(&Bs[0][bRow][bCol]);
    bDst[1] = smem_u32(&Bs[1][bRow][bCol]);
    bDst[2] = smem_u32(&Bs[2][bRow][bCol]);

    float acc[8][8];
#pragma unroll
    for (int i = 0; i < 8; ++i)
#pragma unroll
        for (int j = 0; j < 8; ++j) acc[i][j] = 0.f;

    auto loadA = [&](int k0) -> float4 {
        if (AMODE != 3) {
            return *(const float4*)(aP0 + k0 + aCol);
        } else {
            int kk = k0 + aCol;
            return (kk < 256) ? *(const float4*)(aP0 + kk)
                              : *(const float4*)(aP1 + (kk - 256));
        }
    };

    constexpr int NT = KDIM / 8;

    // prologue: B0, B1 in flight; A0 staged; wait for B0 only
    {
        cp16(bDst[0], bP);
        CP_COMMIT();
        cp16(bDst[1], bP + (size_t)8 * NDIM);
        CP_COMMIT();
        float4 av = loadA(0);
        As[0][aCol + 0][aRow] = av.x;
        As[0][aCol + 1][aRow] = av.y;
        As[0][aCol + 2][aRow] = av.z;
        As[0][aCol + 3][aRow] = av.w;
        CP_WAIT1();                       // <=1 outstanding -> B0 resident
    }
    __syncthreads();

    int cur = 0, nxt = 1, nx2 = 2;
    for (int t = 0; t < NT; ++t) {
        float4 av;
        if (t + 2 < NT) {                 // B(t+2) into the 3rd buffer
            cp16(bDst[nx2], bP + (size_t)((t + 2) * 8) * NDIM);
            CP_COMMIT();
        }
        if (t + 1 < NT) av = loadA((t + 1) * 8);
#pragma unroll
        for (int kk = 0; kk < 8; ++kk) {
            float ra[8], rb[8];
            *(float4*)(ra)     = *(const float4*)&As[cur][kk][tr];
            *(float4*)(ra + 4) = *(const float4*)&As[cur][kk][tr + 4];
            *(float4*)(rb)     = *(const float4*)&Bs[cur][kk][tc];
            *(float4*)(rb + 4) = *(const float4*)&Bs[cur][kk][tc + 4];
#pragma unroll
            for (int i = 0; i < 8; ++i)
#pragma unroll
                for (int j = 0; j < 8; ++j) acc[i][j] += ra[i] * rb[j];
        }
        if (t + 1 < NT) {
            As[nxt][aCol + 0][aRow] = av.x;
            As[nxt][aCol + 1][aRow] = av.y;
            As[nxt][aCol + 2][aRow] = av.z;
            As[nxt][aCol + 3][aRow] = av.w;
            CP_WAIT1();                   // B(t+1) resident; B(t+2) in flight
            __syncthreads();
        }
        int tmp = cur; cur = nxt; nxt = nx2; nx2 = tmp;
    }

#pragma unroll
    for (int i = 0; i < 8; ++i) {
        int mm = m0 + tr + i;
        float* crow = C + (size_t)mm * NDIM + n0 + tc;
        int bi = 0;
        if (EPI == 1) bi = (mm >> 11) & 7;
#pragma unroll
        for (int j4 = 0; j4 < 8; j4 += 4) {
            int col = n0 + tc + j4;
            float4 v = make_float4(acc[i][j4], acc[i][j4 + 1], acc[i][j4 + 2], acc[i][j4 + 3]);
            v.x += bias[col]; v.y += bias[col + 1]; v.z += bias[col + 2]; v.w += bias[col + 3];
            if (EPI == 1) {
                const float* zr = &g_zp[bi * D_];
                v.x = ftanh(v.x + zr[col]);     v.y = ftanh(v.y + zr[col + 1]);
                v.z = ftanh(v.z + zr[col + 2]); v.w = ftanh(v.w + zr[col + 3]);
            }
            *(float4*)(crow + j4) = v;
        }
    }
}

// -------- cluster LSTM scan (R11 proven version, verbatim) -------------------
// 32 clusters x 8 CTAs. Cluster c: dir = c>>4, grp = c&15 -> seqs {2grp,2grp+1}.
// CTA rank r owns hidden units [32r, 32r+32). Wh slice: K-pairs 0..31 of each
// thread's K-half in REGISTERS, pairs 32..63 in SMEM (64KB, [kp][c] layout =
// lane-consecutive, conflict-free). 2 CTAs per SM hide sync/DSMEM latency.
// Per-source chunked mbarrier waits (R8 pattern).
#define SCAN_SMEM (4096 + 4096 + 128 + 65536)
__global__ void __launch_bounds__(256, 2) __cluster_dims__(CL, 1, 1)
k_scan(const float* __restrict__ Whf, const float* __restrict__ Whb) {
    extern __shared__ __align__(16) char smx[];
    float* hbuf = (float*)smx;                 // [buf][s][k]  2*2*256 = 4KB
    ull*   red  = (ull*)(smx + 4096);          // [kh][gate][s][u] 2*4*2*32 = 4KB
    ull*   mbar = (ull*)(smx + 8192);          // [src][buf] 8*2
    ull*   Ws   = (ull*)(smx + 8320);          // [kh][kp2][c] 2*32*128 = 64KB

    const int tid = threadIdx.x;
    const unsigned rank = ctarank();
    const int cid = blockIdx.x >> 3;
    const int dir = cid >> 4;
    const int grp = cid & 15;
    const float* Wh   = dir ? Whb : Whf;
    const float* xw   = dir ? g_xw1 : g_xw0;
    float*       hseq = dir ? g_hseq1 : g_hseq0;
    const int ju0 = (int)rank * 32;

    if (tid < 16)
        mbar_init(smem_u32(&mbar[0]) + (unsigned)tid * 8, 1);

    // ---- Wh slice: regs (k-pairs 0..31 of the K-half) + smem (32..63) ----
    const int kh   = tid >> 7;        // K half (warp-uniform)
    const int c    = tid & 127;       // gate*32 + unit
    const int gate = c >> 5;
    const int u    = c & 31;
    const int gcol = gate * 256 + ju0 + u;
    ull W2[32];
#pragma unroll
    for (int k2 = 0; k2 < 32; ++k2) {
        const int k = kh * 128 + 2 * k2;
        float lo = __ldg(Wh + (size_t)k * G_ + gcol);
        float hi = __ldg(Wh + (size_t)(k + 1) * G_ + gcol);
        PACK2(W2[k2], lo, hi);
    }
    for (int k2 = 0; k2 < 32; ++k2) {
        const int k = kh * 128 + 2 * (32 + k2);
        float lo = __ldg(Wh + (size_t)k * G_ + gcol);
        float hi = __ldg(Wh + (size_t)(k + 1) * G_ + gcol);
        ull w; PACK2(w, lo, hi);
        Ws[(kh * 32 + k2) * 128 + c] = w;
    }
    __syncthreads();
    // mbarriers must be initialized cluster-wide before first arrive
    asm volatile("barrier.cluster.arrive.aligned;" ::: "memory");
    asm volatile("barrier.cluster.wait.aligned;" ::: "memory");

    // ---- epilogue roles (tid<64): es = seq (0/1), ue = unit ----
    const int es = tid >> 5;
    const int ue = tid & 31;
    unsigned pa[CL];
    if (tid < 64) {
        unsigned la = smem_u32(&hbuf[es * 256 + ju0 + ue]);
#pragma unroll
        for (unsigned r = 0; r < CL; ++r) pa[r] = mapa_u32(la, r);
    }
    // thread tid<8 arrives at destination CTA 'tid' on barrier mbar[rank][buf]
    unsigned amD = 0;
    if (tid < CL)
        amD = mapa_u32(smem_u32(&mbar[rank * 2]), (unsigned)tid);
    const int nG = grp * 2 + es;      // global sequence (tid<64)
    float creg = 0.f;

    for (int t = 0; t < S_; ++t) {
        const int buf = t & 1;

        // prefetch this step's input projections (overlaps waits + GEMM)
        float xi = 0.f, xf = 0.f, xg = 0.f, xo = 0.f;
        if (tid < 64) {
            const float* xp = xw + ((size_t)nG * S_ + t) * G_ + ju0 + ue;
            xi = __ldcg(xp);
            xf = __ldcg(xp + 256);
            xg = __ldcg(xp + 512);
            xo = __ldcg(xp + 768);
        }

        ull a0 = 0ull, a1 = 0ull;     // 2 seqs
        if (t > 0) {
            const unsigned par = (unsigned)(((t - 1) >> 1) & 1);
            const unsigned pb  = (unsigned)((t - 1) & 1);
            const float* hball = hbuf + (buf ^ 1) * 512;
            // 4 source chunks of this K-half; wait per chunk before consuming
#pragma unroll
            for (int ci = 0; ci < 4; ++ci) {
                const int src = kh * 4 + ci;
                mbar_wait_cluster(smem_u32(&mbar[src * 2]) + pb * 8, par);
                const float* hb = hball + src * 32;
#pragma unroll
                for (int q = 0; q < 4; ++q) {       // 8 K-values per q
                    ulonglong2 hA0 = *(const ulonglong2*)(hb + q * 8);
                    ulonglong2 hB0 = *(const ulonglong2*)(hb + q * 8 + 4);
                    ulonglong2 hA1 = *(const ulonglong2*)(hb + 256 + q * 8);
                    ulonglong2 hB1 = *(const ulonglong2*)(hb + 256 + q * 8 + 4);
                    ull w0, w1, w2, w3;
                    if (ci < 2) {
                        const int kp = ci * 16 + q * 4;
                        w0 = W2[kp]; w1 = W2[kp + 1]; w2 = W2[kp + 2]; w3 = W2[kp + 3];
                    } else {
                        const ull* wsm = Ws + (kh * 32 + (ci - 2) * 16 + q * 4) * 128 + c;
                        w0 = wsm[0]; w1 = wsm[128]; w2 = wsm[256]; w3 = wsm[384];
                    }
                    FMA2(a0, w0, hA0.x); FMA2(a0, w1, hA0.y);
                    FMA2(a0, w2, hB0.x); FMA2(a0, w3, hB0.y);
                    FMA2(a1, w0, hA1.x); FMA2(a1, w1, hA1.y);
                    FMA2(a1, w2, hB1.x); FMA2(a1, w3, hB1.y);
                }
            }
        }
        red[((kh * 4 + gate) * 2 + 0) * 32 + u] = a0;
        red[((kh * 4 + gate) * 2 + 1) * 32 + u] = a1;
        __syncthreads();

        if (tid < 64) {
            float v[4];
#pragma unroll
            for (int g = 0; g < 4; ++g) {
                float q0, q1, q2, q3;
                UNPK(q0, q1, red[((0 + g) * 2 + es) * 32 + ue]);
                UNPK(q2, q3, red[((4 + g) * 2 + es) * 32 + ue]);
                v[g] = (q0 + q1) + (q2 + q3);
            }
            float gi = v[0] + xi, gf = v[1] + xf, gg = v[2] + xg, go = v[3] + xo;
            float ii = sig_fast(gi), ff = sig_fast(gf);
            float g2 = tanh_fast(gg), oo = sig_fast(go);
            creg = ff * creg + ii * g2;
            float hv = oo * tanh_fast(creg);
            if (t < S_ - 1) {
                const unsigned boff = (unsigned)buf << 11;   // buf*2048 bytes
#pragma unroll
                for (int r = 0; r < CL; ++r) st_cluster_f32(pa[r] + boff, hv);
            }
            __stcg(&hseq[((size_t)t * N_ + nG) * H_ + ju0 + ue], hv);
        }
        __syncthreads();   // all pushes ordered before the release-arrives
        if (t < S_ - 1 && tid < CL)
            mbar_arrive_cluster(amD + (unsigned)buf * 8);
    }

    if (tid == 0) {
#pragma unroll
        for (int i = 0; i < 16; ++i)
            asm volatile("mbarrier.inval.shared.b64 [%0];"
                         :: "r"(smem_u32(&mbar[0]) + i * 8) : "memory");
    }
    // no CTA may exit while peers might still push into its smem
    asm volatile("barrier.cluster.arrive.aligned;" ::: "memory");
    asm volatile("barrier.cluster.wait.aligned;" ::: "memory");
}

// ------------------------------ launcher -------------------------------------
extern "C" void kernel_launch(void* const* d_in, const int* in_sizes, int n_in,
                              void* d_out, int out_size) {
    const float* x   = (const float*)d_in[0];
    const float* W3  = (const float*)d_in[1];
    const float* b3  = (const float*)d_in[2];
    const float* W4  = (const float*)d_in[3];
    const float* b4  = (const float*)d_in[4];
    const float* Wxf = (const float*)d_in[5];
    const float* Whf = (const float*)d_in[6];
    const float* bf  = (const float*)d_in[7];
    const float* Wxb = (const float*)d_in[8];
    const float* Whb = (const float*)d_in[9];
    const float* bb  = (const float*)d_in[10];
    const float* Wd  = (const float*)d_in[11];
    const float* bd  = (const float*)d_in[12];
    float* out = (float*)d_out;

    float *pf, *pxw0, *pxw1, *ph0, *ph1, *phbuf;
    cudaGetSymbolAddress((void**)&pf,    g_f);
    cudaGetSymbolAddress((void**)&pxw0,  g_xw0);
    cudaGetSymbolAddress((void**)&pxw1,  g_xw1);
    cudaGetSymbolAddress((void**)&ph0,   g_hseq0);
    cudaGetSymbolAddress((void**)&ph1,   g_hseq1);
    cudaGetSymbolAddress((void**)&phbuf, g_hbuf);

    cudaFuncSetAttribute(k_scan, cudaFuncAttributeMaxDynamicSharedMemorySize,
                         SCAN_SMEM);

    for (int it = 0; it < 2; ++it) {
        const float* hin = (it == 0) ? x : phbuf;
        float* hout = (it == 1) ? out : phbuf;

        // zp = (sum_a h[:, :, -1, :]/3) @ W4 + b4
        k_zzp<<<B_, D_>>>(hin, W4, b4);
        // f = tanh(h @ W3 + b3 + zp[b])
        k_gemm<0, 1, 256, 256><<<dim3(2, 512), 256>>>(hin, nullptr, W3, b3, pf);
        // gate input projections (fwd + time-reversed bwd)
        k_gemm<0, 0, 256, 1024><<<dim3(8, 512), 256>>>(pf, nullptr, Wxf, bf, pxw0);
        k_gemm<1, 0, 256, 1024><<<dim3(8, 512), 256>>>(pf, nullptr, Wxb, bb, pxw1);
        // cluster-local bidirectional LSTM scan (R11 proven version)
        k_scan<<<32 * CL, 256, SCAN_SMEM>>>(Whf, Whb);
        // h = concat(hf, hb_rev) @ Wd + bd   (hseq in [t][n][j] layout)
        k_gemm<3, 0, 512, 256><<<dim3(2, 512), 256>>>(ph0, ph1, Wd, bd, hout);
    }
}

// round 16
// speedup vs baseline: 2.6920x; 1.0246x over previous
#include <cuda_runtime.h>
#include <cstddef>
#include <cstdint>

typedef unsigned long long ull;

// Problem constants
#define A_ 4
#define B_ 8
#define S_ 2048
#define D_ 256
#define N_ 32      // A_*B_
#define H_ 256
#define G_ 1024    // 4*H_
#define CL 8       // cluster size

// -------- scratch (device globals; allocation-free per harness rules) --------
__device__ float g_f[(size_t)N_ * S_ * D_];
__device__ float g_xw0[(size_t)N_ * S_ * G_];
__device__ float g_xw1[(size_t)N_ * S_ * G_];
__device__ float g_hseq0[(size_t)S_ * N_ * H_];   // [t][n][j] layout
__device__ float g_hseq1[(size_t)S_ * N_ * H_];   // [t][n][j] layout
__device__ float g_hbuf[(size_t)N_ * S_ * D_];
__device__ float g_zp[B_ * D_];

__device__ __forceinline__ float fsig(float x) { return 1.f / (1.f + __expf(-x)); }
__device__ __forceinline__ float ftanh(float x) {
    float t = __expf(-2.f * fabsf(x));
    float r = (1.f - t) / (1.f + t);
    return copysignf(r, x);
}
// fast approx versions for the scan recurrence (MUFU tanh, sm_75+)
__device__ __forceinline__ float tanh_fast(float x) {
    float y; asm("tanh.approx.f32 %0, %1;" : "=f"(y) : "f"(x)); return y;
}
__device__ __forceinline__ float sig_fast(float x) {
    return fmaf(tanh_fast(0.5f * x), 0.5f, 0.5f);
}

// f32x2 packed FFMA (sm_103a; only reachable via PTX)
#define FMA2(acc, a, b) asm("fma.rn.f32x2 %0, %1, %2, %0;" : "+l"(acc) : "l"(a), "l"(b))
#define PACK2(out, lo, hi) \
    asm("mov.b64 %0, {%1, %2};" : "=l"(out) : "f"(lo), "f"(hi))
#define PACKD(out, v)                                                        \
    do { unsigned _u = __float_as_uint(v);                                   \
         asm("mov.b64 %0, {%1, %1};" : "=l"(out) : "r"(_u)); } while (0)
#define UNPK(lo, hi, v)                                                      \
    do { unsigned _a, _b;                                                    \
         asm("mov.b64 {%0, %1}, %2;" : "=r"(_a), "=r"(_b) : "l"(v));         \
         lo = __uint_as_float(_a); hi = __uint_as_float(_b); } while (0)

__device__ __forceinline__ unsigned ctarank() {
    unsigned r; asm("mov.u32 %0, %%cluster_ctarank;" : "=r"(r)); return r;
}
__device__ __forceinline__ unsigned smem_u32(const void* p) {
    return (unsigned)__cvta_generic_to_shared(p);
}
__device__ __forceinline__ unsigned mapa_u32(unsigned a, unsigned rank) {
    unsigned r;
    asm("mapa.shared::cluster.u32 %0, %1, %2;" : "=r"(r) : "r"(a), "r"(rank));
    return r;
}
__device__ __forceinline__ void st_cluster_f32(unsigned a, float v) {
    asm volatile("st.shared::cluster.f32 [%0], %1;" :: "r"(a), "f"(v) : "memory");
}
__device__ __forceinline__ void mbar_init(unsigned a, unsigned cnt) {
    asm volatile("mbarrier.init.shared.b64 [%0], %1;" :: "r"(a), "r"(cnt) : "memory");
}
__device__ __forceinline__ void mbar_arrive_cluster(unsigned a) {
    asm volatile("mbarrier.arrive.release.cluster.shared::cluster.b64 _, [%0];"
                 :: "r"(a) : "memory");
}
__device__ __forceinline__ void mbar_wait_cluster(unsigned a, unsigned parity) {
    asm volatile(
        "{\n\t.reg .pred P;\n\t"
        "W%=:\n\t"
        "mbarrier.try_wait.parity.acquire.cluster.shared::cta.b64 P, [%0], %1, 0x989680;\n\t"
        "@!P bra W%=;\n\t}"
        :: "r"(a), "r"(parity) : "memory");
}

// ------------------------- z / zp (tiny matvec) ------------------------------
__global__ void k_zzp(const float* __restrict__ hin, const float* __restrict__ W4,
                      const float* __restrict__ b4) {
    __shared__ float zs[D_];
    int b = blockIdx.x;
    int e = threadIdx.x;
    float s = 0.f;
#pragma unroll
    for (int a = 0; a < A_; ++a)
        s += hin[(((size_t)(a * B_ + b)) * S_ + (S_ - 1)) * D_ + e];
    zs[e] = s * (1.f / 3.f);
    __syncthreads();
    float acc = b4[e];
#pragma unroll 8
    for (int d = 0; d < D_; ++d) acc += zs[d] * W4[d * D_ + e];
    g_zp[b * D_ + e] = acc;
}

// --------------- SGEMM (double-buffered LDG, FFMA2 inner loop) ---------------
// C[M x NDIM] = op(A)[M x KDIM] @ Bw[KDIM x NDIM] + bias (+ optional zp + tanh)
// AMODE 0: A0[m][k]
// AMODE 1: A0[(n, S-1-s)][k]          (time-reversed rows; m = n*S+s)
// AMODE 3: concat from [t][n][j] layout:
//          k<256 -> A0[(s*32+n)][k] ; k>=256 -> A1[((S-1-s)*32+n)][k-256]
// EPI 0: +bias   EPI 1: tanh(v + bias + g_zp[b])
// R11's proven 2-buffer LDG+STS pipeline (1 BAR/tile, prefetch before the
// FFMA block). Inner product now uses fma.rn.f32x2: 256 FFMA2 + 64 PACKD
// per tile/thread instead of 512 FFMA -> ~35% fewer issue slots on the
// binding fma/issue pipes.
template <int AMODE, int EPI, int KDIM, int NDIM>
__global__ void __launch_bounds__(256, 2)
k_gemm(const float* __restrict__ A0, const float* __restrict__ A1,
       const float* __restrict__ Bw, const float* __restrict__ bias,
       float* __restrict__ C) {
    __shared__ float As[2][8][128];
    __shared__ float Bs[2][8][128];
    const int tid = threadIdx.x;
    const int m0 = blockIdx.y * 128;
    const int n0 = blockIdx.x * 128;
    const int aRow = tid >> 1;
    const int aCol = (tid & 1) * 4;
    const int bRow = tid >> 5;
    const int bCol = (tid & 31) * 4;
    const int tr = (tid >> 4) * 8;
    const int tc = (tid & 15) * 8;

    const int m = m0 + aRow;
    const float* aP0;
    const float* aP1 = nullptr;
    if (AMODE == 0) {
        aP0 = A0 + (size_t)m * KDIM;
    } else if (AMODE == 1) {
        int n = m >> 11, s = m & 2047;
        aP0 = A0 + ((size_t)(n << 11) + (2047 - s)) * KDIM;
    } else {
        int n = m >> 11, s = m & 2047;
        aP0 = A0 + ((size_t)(s * 32) + n) * 256;
        aP1 = A1 + ((size_t)((2047 - s) * 32) + n) * 256;
    }
    const float* bP = Bw + (size_t)bRow * NDIM + n0 + bCol;

    ull acc2[8][4];
#pragma unroll
    for (int i = 0; i < 8; ++i)
#pragma unroll
        for (int j = 0; j < 4; ++j) acc2[i][j] = 0ull;

    auto loadA = [&](int k0) -> float4 {
        if (AMODE != 3) {
            return *(const float4*)(aP0 + k0 + aCol);
        } else {
            int kk = k0 + aCol;
            return (kk < 256) ? *(const float4*)(aP0 + kk)
                              : *(const float4*)(aP1 + (kk - 256));
        }
    };
    auto loadB = [&](int k0) -> float4 {
        return *(const float4*)(bP + (size_t)k0 * NDIM);
    };

    constexpr int NT = KDIM / 8;

    // prologue: tile 0 -> buffer 0
    {
        float4 av = loadA(0);
        float4 bv = loadB(0);
        As[0][aCol + 0][aRow] = av.x;
        As[0][aCol + 1][aRow] = av.y;
        As[0][aCol + 2][aRow] = av.z;
        As[0][aCol + 3][aRow] = av.w;
        *(float4*)&Bs[0][bRow][bCol] = bv;
    }
    __syncthreads();

    for (int t = 0; t < NT; ++t) {
        const int cur = t & 1;
        float4 av, bv;
        if (t + 1 < NT) {             // issue next tile's LDG before compute
            av = loadA((t + 1) * 8);
            bv = loadB((t + 1) * 8);
        }
#pragma unroll
        for (int kk = 0; kk < 8; ++kk) {
            float ra[8];
            *(float4*)(ra)     = *(const float4*)&As[cur][kk][tr];
            *(float4*)(ra + 4) = *(const float4*)&As[cur][kk][tr + 4];
            ulonglong2 rb0 = *(const ulonglong2*)&Bs[cur][kk][tc];
            ulonglong2 rb1 = *(const ulonglong2*)&Bs[cur][kk][tc + 4];
#pragma unroll
            for (int i = 0; i < 8; ++i) {
                ull ap; PACKD(ap, ra[i]);
                FMA2(acc2[i][0], ap, rb0.x);
                FMA2(acc2[i][1], ap, rb0.y);
                FMA2(acc2[i][2], ap, rb1.x);
                FMA2(acc2[i][3], ap, rb1.y);
            }
        }
        if (t + 1 < NT) {             // store into the OTHER buffer; 1 BAR/tile
            const int nxt = cur ^ 1;
            As[nxt][aCol + 0][aRow] = av.x;
            As[nxt][aCol + 1][aRow] = av.y;
            As[nxt][aCol + 2][aRow] = av.z;
            As[nxt][aCol + 3][aRow] = av.w;
            *(float4*)&Bs[nxt][bRow][bCol] = bv;
            __syncthreads();
        }
    }

#pragma unroll
    for (int i = 0; i < 8; ++i) {
        int mm = m0 + tr + i;
        float* crow = C + (size_t)mm * NDIM + n0 + tc;
        int bi = 0;
        if (EPI == 1) bi = (mm >> 11) & 7;
        float cv[8];
#pragma unroll
        for (int j2 = 0; j2 < 4; ++j2) UNPK(cv[2 * j2], cv[2 * j2 + 1], acc2[i][j2]);
#pragma unroll
        for (int j4 = 0; j4 < 8; j4 += 4) {
            int col = n0 + tc + j4;
            float4 v = make_float4(cv[j4], cv[j4 + 1], cv[j4 + 2], cv[j4 + 3]);
            v.x += bias[col]; v.y += bias[col + 1]; v.z += bias[col + 2]; v.w += bias[col + 3];
            if (EPI == 1) {
                const float* zr = &g_zp[bi * D_];
                v.x = ftanh(v.x + zr[col]);     v.y = ftanh(v.y + zr[col + 1]);
                v.z = ftanh(v.z + zr[col + 2]); v.w = ftanh(v.w + zr[col + 3]);
            }
            *(float4*)(crow + j4) = v;
        }
    }
}

// -------- cluster LSTM scan (R11 proven version, verbatim) -------------------
// 32 clusters x 8 CTAs. Cluster c: dir = c>>4, grp = c&15 -> seqs {2grp,2grp+1}.
// CTA rank r owns hidden units [32r, 32r+32). Wh slice: K-pairs 0..31 of each
// thread's K-half in REGISTERS, pairs 32..63 in SMEM (64KB, [kp][c] layout =
// lane-consecutive, conflict-free). 2 CTAs per SM hide sync/DSMEM latency.
// Per-source chunked mbarrier waits (R8 pattern).
#define SCAN_SMEM (4096 + 4096 + 128 + 65536)
__global__ void __launch_bounds__(256, 2) __cluster_dims__(CL, 1, 1)
k_scan(const float* __restrict__ Whf, const float* __restrict__ Whb) {
    extern __shared__ __align__(16) char smx[];
    float* hbuf = (float*)smx;                 // [buf][s][k]  2*2*256 = 4KB
    ull*   red  = (ull*)(smx + 4096);          // [kh][gate][s][u] 2*4*2*32 = 4KB
    ull*   mbar = (ull*)(smx + 8192);          // [src][buf] 8*2
    ull*   Ws   = (ull*)(smx + 8320);          // [kh][kp2][c] 2*32*128 = 64KB

    const int tid = threadIdx.x;
    const unsigned rank = ctarank();
    const int cid = blockIdx.x >> 3;
    const int dir = cid >> 4;
    const int grp = cid & 15;
    const float* Wh   = dir ? Whb : Whf;
    const float* xw   = dir ? g_xw1 : g_xw0;
    float*       hseq = dir ? g_hseq1 : g_hseq0;
    const int ju0 = (int)rank * 32;

    if (tid < 16)
        mbar_init(smem_u32(&mbar[0]) + (unsigned)tid * 8, 1);

    // ---- Wh slice: regs (k-pairs 0..31 of the K-half) + smem (32..63) ----
    const int kh   = tid >> 7;        // K half (warp-uniform)
    const int c    = tid & 127;       // gate*32 + unit
    const int gate = c >> 5;
    const int u    = c & 31;
    const int gcol = gate * 256 + ju0 + u;
    ull W2[32];
#pragma unroll
    for (int k2 = 0; k2 < 32; ++k2) {
        const int k = kh * 128 + 2 * k2;
        float lo = __ldg(Wh + (size_t)k * G_ + gcol);
        float hi = __ldg(Wh + (size_t)(k + 1) * G_ + gcol);
        PACK2(W2[k2], lo, hi);
    }
    for (int k2 = 0; k2 < 32; ++k2) {
        const int k = kh * 128 + 2 * (32 + k2);
        float lo = __ldg(Wh + (size_t)k * G_ + gcol);
        float hi = __ldg(Wh + (size_t)(k + 1) * G_ + gcol);
        ull w; PACK2(w, lo, hi);
        Ws[(kh * 32 + k2) * 128 + c] = w;
    }
    __syncthreads();
    // mbarriers must be initialized cluster-wide before first arrive
    asm volatile("barrier.cluster.arrive.aligned;" ::: "memory");
    asm volatile("barrier.cluster.wait.aligned;" ::: "memory");

    // ---- epilogue roles (tid<64): es = seq (0/1), ue = unit ----
    const int es = tid >> 5;
    const int ue = tid & 31;
    unsigned pa[CL];
    if (tid < 64) {
        unsigned la = smem_u32(&hbuf[es * 256 + ju0 + ue]);
#pragma unroll
        for (unsigned r = 0; r < CL; ++r) pa[r] = mapa_u32(la, r);
    }
    // thread tid<8 arrives at destination CTA 'tid' on barrier mbar[rank][buf]
    unsigned amD = 0;
    if (tid < CL)
        amD = mapa_u32(smem_u32(&mbar[rank * 2]), (unsigned)tid);
    const int nG = grp * 2 + es;      // global sequence (tid<64)
    float creg = 0.f;

    for (int t = 0; t < S_; ++t) {
        const int buf = t & 1;

        // prefetch this step's input projections (overlaps waits + GEMM)
        float xi = 0.f, xf = 0.f, xg = 0.f, xo = 0.f;
        if (tid < 64) {
            const float* xp = xw + ((size_t)nG * S_ + t) * G_ + ju0 + ue;
            xi = __ldcg(xp);
            xf = __ldcg(xp + 256);
            xg = __ldcg(xp + 512);
            xo = __ldcg(xp + 768);
        }

        ull a0 = 0ull, a1 = 0ull;     // 2 seqs
        if (t > 0) {
            const unsigned par = (unsigned)(((t - 1) >> 1) & 1);
            const unsigned pb  = (unsigned)((t - 1) & 1);
            const float* hball = hbuf + (buf ^ 1) * 512;
            // 4 source chunks of this K-half; wait per chunk before consuming
#pragma unroll
            for (int ci = 0; ci < 4; ++ci) {
                const int src = kh * 4 + ci;
                mbar_wait_cluster(smem_u32(&mbar[src * 2]) + pb * 8, par);
                const float* hb = hball + src * 32;
#pragma unroll
                for (int q = 0; q < 4; ++q) {       // 8 K-values per q
                    ulonglong2 hA0 = *(const ulonglong2*)(hb + q * 8);
                    ulonglong2 hB0 = *(const ulonglong2*)(hb + q * 8 + 4);
                    ulonglong2 hA1 = *(const ulonglong2*)(hb + 256 + q * 8);
                    ulonglong2 hB1 = *(const ulonglong2*)(hb + 256 + q * 8 + 4);
                    ull w0, w1, w2, w3;
                    if (ci < 2) {
                        const int kp = ci * 16 + q * 4;
                        w0 = W2[kp]; w1 = W2[kp + 1]; w2 = W2[kp + 2]; w3 = W2[kp + 3];
                    } else {
                        const ull* wsm = Ws + (kh * 32 + (ci - 2) * 16 + q * 4) * 128 + c;
                        w0 = wsm[0]; w1 = wsm[128]; w2 = wsm[256]; w3 = wsm[384];
                    }
                    FMA2(a0, w0, hA0.x); FMA2(a0, w1, hA0.y);
                    FMA2(a0, w2, hB0.x); FMA2(a0, w3, hB0.y);
                    FMA2(a1, w0, hA1.x); FMA2(a1, w1, hA1.y);
                    FMA2(a1, w2, hB1.x); FMA2(a1, w3, hB1.y);
                }
            }
        }
        red[((kh * 4 + gate) * 2 + 0) * 32 + u] = a0;
        red[((kh * 4 + gate) * 2 + 1) * 32 + u] = a1;
        __syncthreads();

        if (tid < 64) {
            float v[4];
#pragma unroll
            for (int g = 0; g < 4; ++g) {
                float q0, q1, q2, q3;
                UNPK(q0, q1, red[((0 + g) * 2 + es) * 32 + ue]);
                UNPK(q2, q3, red[((4 + g) * 2 + es) * 32 + ue]);
                v[g] = (q0 + q1) + (q2 + q3);
            }
            float gi = v[0] + xi, gf = v[1] + xf, gg = v[2] + xg, go = v[3] + xo;
            float ii = sig_fast(gi), ff = sig_fast(gf);
            float g2 = tanh_fast(gg), oo = sig_fast(go);
            creg = ff * creg + ii * g2;
            float hv = oo * tanh_fast(creg);
            if (t < S_ - 1) {
                const unsigned boff = (unsigned)buf << 11;   // buf*2048 bytes
#pragma unroll
                for (int r = 0; r < CL; ++r) st_cluster_f32(pa[r] + boff, hv);
            }
            __stcg(&hseq[((size_t)t * N_ + nG) * H_ + ju0 + ue], hv);
        }
        __syncthreads();   // all pushes ordered before the release-arrives
        if (t < S_ - 1 && tid < CL)
            mbar_arrive_cluster(amD + (unsigned)buf * 8);
    }

    if (tid == 0) {
#pragma unroll
        for (int i = 0; i < 16; ++i)
            asm volatile("mbarrier.inval.shared.b64 [%0];"
                         :: "r"(smem_u32(&mbar[0]) + i * 8) : "memory");
    }
    // no CTA may exit while peers might still push into its smem
    asm volatile("barrier.cluster.arrive.aligned;" ::: "memory");
    asm volatile("barrier.cluster.wait.aligned;" ::: "memory");
}

// ------------------------------ launcher -------------------------------------
extern "C" void kernel_launch(void* const* d_in, const int* in_sizes, int n_in,
                              void* d_out, int out_size) {
    const float* x   = (const float*)d_in[0];
    const float* W3  = (const float*)d_in[1];
    const float* b3  = (const float*)d_in[2];
    const float* W4  = (const float*)d_in[3];
    const float* b4  = (const float*)d_in[4];
    const float* Wxf = (const float*)d_in[5];
    const float* Whf = (const float*)d_in[6];
    const float* bf  = (const float*)d_in[7];
    const float* Wxb = (const float*)d_in[8];
    const float* Whb = (const float*)d_in[9];
    const float* bb  = (const float*)d_in[10];
    const float* Wd  = (const float*)d_in[11];
    const float* bd  = (const float*)d_in[12];
    float* out = (float*)d_out;

    float *pf, *pxw0, *pxw1, *ph0, *ph1, *phbuf;
    cudaGetSymbolAddress((void**)&pf,    g_f);
    cudaGetSymbolAddress((void**)&pxw0,  g_xw0);
    cudaGetSymbolAddress((void**)&pxw1,  g_xw1);
    cudaGetSymbolAddress((void**)&ph0,   g_hseq0);
    cudaGetSymbolAddress((void**)&ph1,   g_hseq1);
    cudaGetSymbolAddress((void**)&phbuf, g_hbuf);

    cudaFuncSetAttribute(k_scan, cudaFuncAttributeMaxDynamicSharedMemorySize,
                         SCAN_SMEM);

    for (int it = 0; it < 2; ++it) {
        const float* hin = (it == 0) ? x : phbuf;
        float* hout = (it == 1) ? out : phbuf;

        // zp = (sum_a h[:, :, -1, :]/3) @ W4 + b4
        k_zzp<<<B_, D_>>>(hin, W4, b4);
        // f = tanh(h @ W3 + b3 + zp[b])
        k_gemm<0, 1, 256, 256><<<dim3(2, 512), 256>>>(hin, nullptr, W3, b3, pf);
        // gate input projections (fwd + time-reversed bwd)
        k_gemm<0, 0, 256, 1024><<<dim3(8, 512), 256>>>(pf, nullptr, Wxf, bf, pxw0);
        k_gemm<1, 0, 256, 1024><<<dim3(8, 512), 256>>>(pf, nullptr, Wxb, bb, pxw1);
        // cluster-local bidirectional LSTM scan (R11 proven version)
        k_scan<<<32 * CL, 256, SCAN_SMEM>>>(Whf, Whb);
        // h = concat(hf, hb_rev) @ Wd + bd   (hseq in [t][n][j] layout)
        k_gemm<3, 0, 512, 256><<<dim3(2, 512), 256>>>(ph0, ph1, Wd, bd, hout);
    }
}